// round 1
// baseline (speedup 1.0000x reference)
#include <cuda_runtime.h>
#include <mma.h>
#include <math.h>

using namespace nvcuda;

// ---------------- problem constants ----------------
#define Bb   8
#define Ss   920
#define Dd   1536
#define Hh   4
#define HDd  384
#define Ll   1839          // 2*920-1
#define BH   32            // Bb*Hh
#define MQ   (BH*Ss)       // 29440
#define HALF 919           // Ll/2

// ---------------- GEMM tiling ----------------
#define BM 128
#define BN 128
#define BK 16
#define NTHREADS 256

// ---------------- scratch (static device globals; no cudaMalloc allowed) ----
__device__ float g_q[BH * Ss * HDd];           // (b,h,s,d)  scaled by 1/sqrt(HD)
__device__ float g_k[BH * Ss * HDd];
__device__ float g_v[BH * Ss * HDd];
__device__ float g_r[54140160];                // MQ * Ll : R[m,l] = Q[m]·de[l]
__device__ float g_s[27084800];                // MQ * Ss : scores / probs

// =======================================================================
// Generic tf32 WMMA GEMM, C = A(MxK, row) * B, 128x128x16 tiles, 8 warps.
// BNT=true : B given as (N x K) row-major  (i.e. C = A * B^T)
// BNT=false: B given as (K x N) row-major  (i.e. C = A * B)
// EPI 0: C[z*sC + m*N + n] = v*scale
// EPI 1: QKV head-split: m->(b,s), n->(h,d): C[((b*H+h)*S+s)*HD+d] = v*scale
// EPI 2: ctx output: z->(b,h), m->s, n->d: C[(b*S+s)*(H*HD) + h*HD + d] = v
// =======================================================================
template<bool BNT, int EPI>
__global__ __launch_bounds__(NTHREADS)
void gemm_tf32(const float* __restrict__ A,
               const float* __restrict__ Bm,
               float* __restrict__ C,
               int M, int N, int K,
               long long strA, long long strB, long long strC,
               float scale)
{
    extern __shared__ float sm[];
    float* shA = sm;               // [BM][20]
    float* shB = sm + BM * 20;     // NT: [BN][20]   NN: [BK][132]

    const int z = blockIdx.z;
    A  += (long long)z * strA;
    Bm += (long long)z * strB;

    const int tid  = threadIdx.x;
    const int warp = tid >> 5;
    const int wm   = warp >> 2;    // 0..1  (64 rows each)
    const int wn   = warp & 3;     // 0..3  (32 cols each)

    const int m0 = blockIdx.y * BM;
    const int n0 = blockIdx.x * BN;

    const int ldb = BNT ? K : N;

    wmma::fragment<wmma::accumulator, 16, 16, 8, float> acc[4][2];
    #pragma unroll
    for (int i = 0; i < 4; i++)
        #pragma unroll
        for (int j = 0; j < 2; j++)
            wmma::fill_fragment(acc[i][j], 0.0f);

    for (int k0 = 0; k0 < K; k0 += BK) {
        // ---- load A tile (BM x BK), zero-fill OOB ----
        #pragma unroll
        for (int e = tid; e < BM * BK; e += NTHREADS) {
            int r = e >> 4, c = e & 15;
            int gm = m0 + r, gk = k0 + c;
            float v = 0.0f;
            if (gm < M && gk < K) v = A[(long long)gm * K + gk];
            shA[r * 20 + c] = v;
        }
        // ---- load B tile ----
        if (BNT) {
            #pragma unroll
            for (int e = tid; e < BN * BK; e += NTHREADS) {
                int r = e >> 4, c = e & 15;
                int gn = n0 + r, gk = k0 + c;
                float v = 0.0f;
                if (gn < N && gk < K) v = Bm[(long long)gn * ldb + gk];
                shB[r * 20 + c] = v;
            }
        } else {
            #pragma unroll
            for (int e = tid; e < BK * BN; e += NTHREADS) {
                int r = e >> 7, c = e & 127;
                int gk = k0 + r, gn = n0 + c;
                float v = 0.0f;
                if (gk < K && gn < N) v = Bm[(long long)gk * ldb + gn];
                shB[r * 132 + c] = v;
            }
        }
        __syncthreads();

        #pragma unroll
        for (int kk = 0; kk < BK; kk += 8) {
            wmma::fragment<wmma::matrix_a, 16, 16, 8, wmma::precision::tf32, wmma::row_major> af[4];
            #pragma unroll
            for (int i = 0; i < 4; i++) {
                wmma::load_matrix_sync(af[i], &shA[(wm * 64 + i * 16) * 20 + kk], 20);
                #pragma unroll
                for (int t = 0; t < af[i].num_elements; t++)
                    af[i].x[t] = wmma::__float_to_tf32(af[i].x[t]);
            }
            if (BNT) {
                wmma::fragment<wmma::matrix_b, 16, 16, 8, wmma::precision::tf32, wmma::col_major> bf[2];
                #pragma unroll
                for (int j = 0; j < 2; j++) {
                    wmma::load_matrix_sync(bf[j], &shB[(wn * 32 + j * 16) * 20 + kk], 20);
                    #pragma unroll
                    for (int t = 0; t < bf[j].num_elements; t++)
                        bf[j].x[t] = wmma::__float_to_tf32(bf[j].x[t]);
                }
                #pragma unroll
                for (int i = 0; i < 4; i++)
                    #pragma unroll
                    for (int j = 0; j < 2; j++)
                        wmma::mma_sync(acc[i][j], af[i], bf[j], acc[i][j]);
            } else {
                wmma::fragment<wmma::matrix_b, 16, 16, 8, wmma::precision::tf32, wmma::row_major> bf[2];
                #pragma unroll
                for (int j = 0; j < 2; j++) {
                    wmma::load_matrix_sync(bf[j], &shB[kk * 132 + wn * 32 + j * 16], 132);
                    #pragma unroll
                    for (int t = 0; t < bf[j].num_elements; t++)
                        bf[j].x[t] = wmma::__float_to_tf32(bf[j].x[t]);
                }
                #pragma unroll
                for (int i = 0; i < 4; i++)
                    #pragma unroll
                    for (int j = 0; j < 2; j++)
                        wmma::mma_sync(acc[i][j], af[i], bf[j], acc[i][j]);
            }
        }
        __syncthreads();
    }

    // ---- stage C in shared (reuses A/B region), then mapped write ----
    float* shC = sm;   // [BM][132]
    #pragma unroll
    for (int i = 0; i < 4; i++)
        #pragma unroll
        for (int j = 0; j < 2; j++)
            wmma::store_matrix_sync(&shC[(wm * 64 + i * 16) * 132 + (wn * 32 + j * 16)],
                                    acc[i][j], 132, wmma::mem_row_major);
    __syncthreads();

    for (int e = tid; e < BM * BN; e += NTHREADS) {
        int i = e >> 7, j = e & 127;
        int gm = m0 + i, gn = n0 + j;
        if (gm >= M || gn >= N) continue;
        float v = shC[i * 132 + j] * scale;
        if (EPI == 0) {
            C[(long long)z * strC + (long long)gm * N + gn] = v;
        } else if (EPI == 1) {
            int b = gm / Ss, s = gm - b * Ss;
            int h = gn / HDd, d = gn - h * HDd;
            C[(((long long)(b * Hh + h)) * Ss + s) * HDd + d] = v;
        } else { // EPI == 2
            int b = z >> 2, h = z & 3;
            C[((long long)b * Ss + gm) * (Hh * HDd) + h * HDd + gn] = v;
        }
    }
}

// =======================================================================
// bias + softmax over each score row:
//   scores[r, k] += R[r, k - q + 919]   (r = bh*920 + q)
//   then row softmax, in place.
// =======================================================================
__global__ __launch_bounds__(256)
void bias_softmax(float* __restrict__ sc, const float* __restrict__ R)
{
    const int r = blockIdx.x;          // 0 .. MQ-1
    const int q = r % Ss;
    float* row = sc + (long long)r * Ss;
    const float* rrow = R + (long long)r * Ll + (HALF - q);   // index by k directly

    const int tid = threadIdx.x;
    __shared__ float red[256];

    float vals[4];
    float mx = -1e30f;
    #pragma unroll
    for (int i = 0; i < 4; i++) {
        int k = tid + i * 256;
        float v = -1e30f;
        if (k < Ss) v = row[k] + rrow[k];
        vals[i] = v;
        mx = fmaxf(mx, v);
    }
    red[tid] = mx; __syncthreads();
    #pragma unroll
    for (int s = 128; s > 0; s >>= 1) {
        if (tid < s) red[tid] = fmaxf(red[tid], red[tid + s]);
        __syncthreads();
    }
    mx = red[0];
    __syncthreads();

    float sum = 0.0f;
    #pragma unroll
    for (int i = 0; i < 4; i++) {
        int k = tid + i * 256;
        float e = 0.0f;
        if (k < Ss) e = __expf(vals[i] - mx);
        vals[i] = e;
        sum += e;
    }
    red[tid] = sum; __syncthreads();
    #pragma unroll
    for (int s = 128; s > 0; s >>= 1) {
        if (tid < s) red[tid] += red[tid + s];
        __syncthreads();
    }
    const float inv = 1.0f / red[0];
    #pragma unroll
    for (int i = 0; i < 4; i++) {
        int k = tid + i * 256;
        if (k < Ss) row[k] = vals[i] * inv;
    }
}

// =======================================================================
extern "C" void kernel_launch(void* const* d_in, const int* in_sizes, int n_in,
                              void* d_out, int out_size)
{
    (void)in_sizes; (void)n_in; (void)out_size;
    const float* hs = (const float*)d_in[0];
    const float* wq = (const float*)d_in[1];
    const float* wk = (const float*)d_in[2];
    const float* wv = (const float*)d_in[3];
    const float* de = (const float*)d_in[4];
    float* out = (float*)d_out;

    float *q, *k, *v, *r, *s;
    cudaGetSymbolAddress((void**)&q, g_q);
    cudaGetSymbolAddress((void**)&k, g_k);
    cudaGetSymbolAddress((void**)&v, g_v);
    cudaGetSymbolAddress((void**)&r, g_r);
    cudaGetSymbolAddress((void**)&s, g_s);

    const int smem = 128 * 132 * (int)sizeof(float);   // 67584 B (>48K)
    cudaFuncSetAttribute(gemm_tf32<false, 1>, cudaFuncAttributeMaxDynamicSharedMemorySize, smem);
    cudaFuncSetAttribute(gemm_tf32<true,  0>, cudaFuncAttributeMaxDynamicSharedMemorySize, smem);
    cudaFuncSetAttribute(gemm_tf32<false, 2>, cudaFuncAttributeMaxDynamicSharedMemorySize, smem);

    const float inv = 1.0f / sqrtf((float)HDd);
    dim3 blk(NTHREADS);

    // 1) QKV projections: X(7360x1536) @ W(1536x1536), head-split outputs
    dim3 gA((Hh * HDd + BN - 1) / BN, (Bb * Ss + BM - 1) / BM, 1);   // (12, 58)
    gemm_tf32<false, 1><<<gA, blk, smem>>>(hs, wq, q, Bb * Ss, Hh * HDd, Dd, 0, 0, 0, inv);
    gemm_tf32<false, 1><<<gA, blk, smem>>>(hs, wk, k, Bb * Ss, Hh * HDd, Dd, 0, 0, 0, 1.0f);
    gemm_tf32<false, 1><<<gA, blk, smem>>>(hs, wv, v, Bb * Ss, Hh * HDd, Dd, 0, 0, 0, 1.0f);

    // 2) R = Q @ DE^T : (29440 x 1839), K = 384
    dim3 gR((Ll + BN - 1) / BN, (MQ + BM - 1) / BM, 1);              // (15, 230)
    gemm_tf32<true, 0><<<gR, blk, smem>>>(q, de, r, MQ, Ll, HDd, 0, 0, 0, 1.0f);

    // 3) scores = Q @ K^T per (b,h): 32 x (920 x 920), K = 384
    dim3 gS((Ss + BN - 1) / BN, (Ss + BM - 1) / BM, BH);             // (8, 8, 32)
    gemm_tf32<true, 0><<<gS, blk, smem>>>(q, k, s, Ss, Ss, HDd,
                                          (long long)Ss * HDd, (long long)Ss * HDd,
                                          (long long)Ss * Ss, 1.0f);

    // 4) bias add (rotated rel-pos) + row softmax, in place
    bias_softmax<<<MQ, 256>>>(s, r);

    // 5) ctx = P @ V per (b,h), write into (B, S, H*HD) output layout
    dim3 gO((HDd + BN - 1) / BN, (Ss + BM - 1) / BM, BH);            // (3, 8, 32)
    gemm_tf32<false, 2><<<gO, blk, smem>>>(s, v, out, Ss, HDd, Ss,
                                           (long long)Ss * Ss, (long long)Ss * HDd,
                                           0, 1.0f);
}

// round 2
// speedup vs baseline: 1.2209x; 1.2209x over previous
#include <cuda_runtime.h>
#include <mma.h>
#include <math.h>
#include <cstdint>

using namespace nvcuda;

// ---------------- problem constants ----------------
#define Bb   8
#define Ss   920
#define Dd   1536
#define Hh   4
#define HDd  384
#define Ll   1839          // 2*920-1
#define BH   32            // Bb*Hh
#define MQ   (BH*Ss)       // 29440
#define HALF 919           // Ll/2

// ---------------- GEMM tiling ----------------
#define BM 128
#define BN 128
#define BK 16
#define NTHREADS 256

// ---------------- scratch (static device globals; no cudaMalloc allowed) ----
__device__ float g_q[BH * Ss * HDd];           // (b,h,s,d)  scaled by 1/sqrt(HD)
__device__ float g_k[BH * Ss * HDd];
__device__ float g_v[BH * Ss * HDd];
__device__ float g_r[54140160];                // MQ * Ll : R[m,l] = Q[m]·de[l]
__device__ float g_s[27084800];                // MQ * Ss : scores / probs

// 16-byte cp.async with zero-fill when pred==false
__device__ __forceinline__ void cp16(float* dst, const float* src, bool pred) {
    uint32_t d = (uint32_t)__cvta_generic_to_shared(dst);
    int sz = pred ? 16 : 0;
    asm volatile("cp.async.cg.shared.global [%0], [%1], 16, %2;\n" :: "r"(d), "l"(src), "r"(sz));
}
__device__ __forceinline__ void cp_commit() { asm volatile("cp.async.commit_group;\n"); }
__device__ __forceinline__ void cp_wait0()  { asm volatile("cp.async.wait_group 0;\n"); }

// =======================================================================
// tf32 WMMA GEMM, C = A(MxK,row) * B, 128x128x16 tiles, double-buffered
// cp.async pipeline, tf32 pre-conversion in smem.
// BNT=true : B is (N x K) row-major  (C = A * B^T)
// BNT=false: B is (K x N) row-major  (C = A * B)
// EPI 0: C[z*sC + m*N + n] = v*scale
// EPI 1: fused QKV: z selects (Bm,C,scale) among {B/C, B1/C1, B2/C2};
//        head-split: m->(b,s), n->(h,d): C[((b*H+h)*S+s)*HD+d] = v*scale
// EPI 2: ctx: z->(b,h), m->s, n->d: C[(b*S+s)*(H*HD) + h*HD + n] = v
// =======================================================================
template<bool BNT, int EPI>
__global__ __launch_bounds__(NTHREADS)
void gemm_tf32(const float* __restrict__ A,
               const float* __restrict__ Bm,
               float* __restrict__ C,
               int M, int N, int K,
               long long strA, long long strB, long long strC,
               float scale,
               const float* __restrict__ B1, const float* __restrict__ B2,
               float* __restrict__ C1, float* __restrict__ C2)
{
    extern __shared__ float sm[];
    // double-buffered stages
    float* shA = sm;                        // [2][BM*20]
    float* shB = sm + 2 * BM * 20;          // NT: [2][BN*20]  NN: [2][BK*132]

    const int z = blockIdx.z;
    A  += (long long)z * strA;
    if (EPI == 1) {
        if (z == 1)      { Bm = B1; C = C1; scale = 1.0f; }
        else if (z == 2) { Bm = B2; C = C2; scale = 1.0f; }
    } else {
        Bm += (long long)z * strB;
    }

    const int tid  = threadIdx.x;
    const int warp = tid >> 5;
    const int wm   = warp >> 2;    // 0..1  (64 rows each)
    const int wn   = warp & 3;     // 0..3  (32 cols each)

    const int m0 = blockIdx.y * BM;
    const int n0 = blockIdx.x * BN;

    const int nIter = (K + BK - 1) / BK;
    const int bStageSz = BNT ? (BN * 20) : (BK * 132);

    wmma::fragment<wmma::accumulator, 16, 16, 8, float> acc[4][2];
    #pragma unroll
    for (int i = 0; i < 4; i++)
        #pragma unroll
        for (int j = 0; j < 2; j++)
            wmma::fill_fragment(acc[i][j], 0.0f);

    // ---- stage issue helpers ----
    auto issue_stage = [&](int k0, int buf) {
        float* dA = shA + buf * (BM * 20);
        float* dB = shB + buf * bStageSz;
        // A tile: BM x BK, 512 16B-chunks
        #pragma unroll
        for (int t = 0; t < 2; t++) {
            int idx = tid + t * NTHREADS;
            int r = idx >> 2, ch = idx & 3;
            int gm = m0 + r, gk = k0 + ch * 4;
            bool p = (gm < M) && (gk < K);
            const float* src = A + (long long)(p ? gm : 0) * K + (p ? gk : 0);
            cp16(&dA[r * 20 + ch * 4], src, p);
        }
        if (BNT) {
            #pragma unroll
            for (int t = 0; t < 2; t++) {
                int idx = tid + t * NTHREADS;
                int r = idx >> 2, ch = idx & 3;
                int gn = n0 + r, gk = k0 + ch * 4;
                bool p = (gn < N) && (gk < K);
                const float* src = Bm + (long long)(p ? gn : 0) * K + (p ? gk : 0);
                cp16(&dB[r * 20 + ch * 4], src, p);
            }
        } else {
            #pragma unroll
            for (int t = 0; t < 2; t++) {
                int idx = tid + t * NTHREADS;
                int r = idx >> 5, ch = idx & 31;
                int gk = k0 + r, gn = n0 + ch * 4;
                bool p = (gk < K) && (gn < N);
                const float* src = Bm + (long long)(p ? gk : 0) * N + (p ? gn : 0);
                cp16(&dB[r * 132 + ch * 4], src, p);
            }
        }
        cp_commit();
    };

    // prologue
    issue_stage(0, 0);

    for (int it = 0; it < nIter; ++it) {
        const int buf = it & 1;
        float* cA = shA + buf * (BM * 20);
        float* cB = shB + buf * bStageSz;

        cp_wait0();
        __syncthreads();              // buffer 'buf' ready; prior mma done everywhere

        if (it + 1 < nIter) issue_stage((it + 1) * BK, buf ^ 1);

        // ---- convert current buffers to tf32 (RNE) in place ----
        #pragma unroll
        for (int t = 0; t < 8; t++) {
            int e = tid + t * NTHREADS;          // 0..2047
            int r = e >> 4, c = e & 15;
            float* p = &cA[r * 20 + c];
            *p = wmma::__float_to_tf32(*p);
        }
        if (BNT) {
            #pragma unroll
            for (int t = 0; t < 8; t++) {
                int e = tid + t * NTHREADS;
                int r = e >> 4, c = e & 15;
                float* p = &cB[r * 20 + c];
                *p = wmma::__float_to_tf32(*p);
            }
        } else {
            #pragma unroll
            for (int t = 0; t < 8; t++) {
                int e = tid + t * NTHREADS;      // 16x128
                int r = e >> 7, c = e & 127;
                float* p = &cB[r * 132 + c];
                *p = wmma::__float_to_tf32(*p);
            }
        }
        __syncthreads();

        // ---- MMA on current buffer ----
        #pragma unroll
        for (int kk = 0; kk < BK; kk += 8) {
            wmma::fragment<wmma::matrix_a, 16, 16, 8, wmma::precision::tf32, wmma::row_major> af[4];
            #pragma unroll
            for (int i = 0; i < 4; i++)
                wmma::load_matrix_sync(af[i], &cA[(wm * 64 + i * 16) * 20 + kk], 20);
            if (BNT) {
                wmma::fragment<wmma::matrix_b, 16, 16, 8, wmma::precision::tf32, wmma::col_major> bf[2];
                #pragma unroll
                for (int j = 0; j < 2; j++)
                    wmma::load_matrix_sync(bf[j], &cB[(wn * 32 + j * 16) * 20 + kk], 20);
                #pragma unroll
                for (int i = 0; i < 4; i++)
                    #pragma unroll
                    for (int j = 0; j < 2; j++)
                        wmma::mma_sync(acc[i][j], af[i], bf[j], acc[i][j]);
            } else {
                wmma::fragment<wmma::matrix_b, 16, 16, 8, wmma::precision::tf32, wmma::row_major> bf[2];
                #pragma unroll
                for (int j = 0; j < 2; j++)
                    wmma::load_matrix_sync(bf[j], &cB[kk * 132 + wn * 32 + j * 16], 132);
                #pragma unroll
                for (int i = 0; i < 4; i++)
                    #pragma unroll
                    for (int j = 0; j < 2; j++)
                        wmma::mma_sync(acc[i][j], af[i], bf[j], acc[i][j]);
            }
        }
    }
    __syncthreads();

    // ---- stage C in shared (reuses stage region), then mapped write ----
    float* shC = sm;   // [BM][132]
    #pragma unroll
    for (int i = 0; i < 4; i++)
        #pragma unroll
        for (int j = 0; j < 2; j++)
            wmma::store_matrix_sync(&shC[(wm * 64 + i * 16) * 132 + (wn * 32 + j * 16)],
                                    acc[i][j], 132, wmma::mem_row_major);
    __syncthreads();

    #pragma unroll 4
    for (int e = tid; e < BM * BN; e += NTHREADS) {
        int i = e >> 7, j = e & 127;
        int gm = m0 + i, gn = n0 + j;
        if (gm >= M || gn >= N) continue;
        float v = shC[i * 132 + j] * scale;
        if (EPI == 0) {
            C[(long long)z * strC + (long long)gm * N + gn] = v;
        } else if (EPI == 1) {
            int b = gm / Ss, s = gm - b * Ss;
            int h = gn / HDd, d = gn - h * HDd;
            C[(((long long)(b * Hh + h)) * Ss + s) * HDd + d] = v;
        } else { // EPI == 2
            int b = z >> 2, h = z & 3;
            C[((long long)b * Ss + gm) * (Hh * HDd) + h * HDd + gn] = v;
        }
    }
}

// =======================================================================
// bias + softmax over each score row:
//   scores[r, k] += R[r, k - q + 919]   (r = bh*920 + q), then row softmax
// =======================================================================
__global__ __launch_bounds__(256)
void bias_softmax(float* __restrict__ sc, const float* __restrict__ R)
{
    const int r = blockIdx.x;          // 0 .. MQ-1
    const int q = r % Ss;
    float* row = sc + (long long)r * Ss;
    const float* rrow = R + (long long)r * Ll + (HALF - q);

    const int tid  = threadIdx.x;
    const int lane = tid & 31;
    const int wid  = tid >> 5;
    __shared__ float wred[8];

    float vals[4];
    float mx = -1e30f;
    #pragma unroll
    for (int i = 0; i < 4; i++) {
        int k = tid + i * 256;
        float v = -1e30f;
        if (k < Ss) v = row[k] + rrow[k];
        vals[i] = v;
        mx = fmaxf(mx, v);
    }
    #pragma unroll
    for (int o = 16; o > 0; o >>= 1) mx = fmaxf(mx, __shfl_xor_sync(0xffffffffu, mx, o));
    if (lane == 0) wred[wid] = mx;
    __syncthreads();
    mx = wred[0];
    #pragma unroll
    for (int w = 1; w < 8; w++) mx = fmaxf(mx, wred[w]);
    __syncthreads();

    float sum = 0.0f;
    #pragma unroll
    for (int i = 0; i < 4; i++) {
        int k = tid + i * 256;
        float e = 0.0f;
        if (k < Ss) e = __expf(vals[i] - mx);
        vals[i] = e;
        sum += e;
    }
    #pragma unroll
    for (int o = 16; o > 0; o >>= 1) sum += __shfl_xor_sync(0xffffffffu, sum, o);
    if (lane == 0) wred[wid] = sum;
    __syncthreads();
    sum = 0.0f;
    #pragma unroll
    for (int w = 0; w < 8; w++) sum += wred[w];

    const float inv = 1.0f / sum;
    #pragma unroll
    for (int i = 0; i < 4; i++) {
        int k = tid + i * 256;
        if (k < Ss) row[k] = vals[i] * inv;
    }
}

// =======================================================================
extern "C" void kernel_launch(void* const* d_in, const int* in_sizes, int n_in,
                              void* d_out, int out_size)
{
    (void)in_sizes; (void)n_in; (void)out_size;
    const float* hs = (const float*)d_in[0];
    const float* wq = (const float*)d_in[1];
    const float* wk = (const float*)d_in[2];
    const float* wv = (const float*)d_in[3];
    const float* de = (const float*)d_in[4];
    float* out = (float*)d_out;

    float *q, *k, *v, *r, *s;
    cudaGetSymbolAddress((void**)&q, g_q);
    cudaGetSymbolAddress((void**)&k, g_k);
    cudaGetSymbolAddress((void**)&v, g_v);
    cudaGetSymbolAddress((void**)&r, g_r);
    cudaGetSymbolAddress((void**)&s, g_s);

    const int smem = 128 * 132 * (int)sizeof(float);   // 67584 B (union of stages / shC)
    cudaFuncSetAttribute(gemm_tf32<false, 1>, cudaFuncAttributeMaxDynamicSharedMemorySize, smem);
    cudaFuncSetAttribute(gemm_tf32<true,  0>, cudaFuncAttributeMaxDynamicSharedMemorySize, smem);
    cudaFuncSetAttribute(gemm_tf32<false, 2>, cudaFuncAttributeMaxDynamicSharedMemorySize, smem);

    const float inv = 1.0f / sqrtf((float)HDd);
    dim3 blk(NTHREADS);

    // 1) fused QKV projections: X(7360x1536) @ {Wq,Wk,Wv}(1536x1536), head-split
    dim3 gA((Hh * HDd + BN - 1) / BN, (Bb * Ss + BM - 1) / BM, 3);   // (12, 58, 3)
    gemm_tf32<false, 1><<<gA, blk, smem>>>(hs, wq, q, Bb * Ss, Hh * HDd, Dd, 0, 0, 0, inv,
                                           wk, wv, k, v);

    // 2) R = Q @ DE^T : (29440 x 1839), K = 384
    dim3 gR((Ll + BN - 1) / BN, (MQ + BM - 1) / BM, 1);              // (15, 230)
    gemm_tf32<true, 0><<<gR, blk, smem>>>(q, de, r, MQ, Ll, HDd, 0, 0, 0, 1.0f,
                                          nullptr, nullptr, nullptr, nullptr);

    // 3) scores = Q @ K^T per (b,h): 32 x (920 x 920), K = 384
    dim3 gS((Ss + BN - 1) / BN, (Ss + BM - 1) / BM, BH);             // (8, 8, 32)
    gemm_tf32<true, 0><<<gS, blk, smem>>>(q, k, s, Ss, Ss, HDd,
                                          (long long)Ss * HDd, (long long)Ss * HDd,
                                          (long long)Ss * Ss, 1.0f,
                                          nullptr, nullptr, nullptr, nullptr);

    // 4) bias add (rotated rel-pos) + row softmax, in place
    bias_softmax<<<MQ, 256>>>(s, r);

    // 5) ctx = P @ V per (b,h), write into (B, S, H*HD) output layout
    dim3 gO((HDd + BN - 1) / BN, (Ss + BM - 1) / BM, BH);            // (3, 8, 32)
    gemm_tf32<false, 2><<<gO, blk, smem>>>(s, v, out, Ss, HDd, Ss,
                                           (long long)Ss * Ss, (long long)Ss * HDd,
                                           0, 1.0f,
                                           nullptr, nullptr, nullptr, nullptr);
}

// round 3
// speedup vs baseline: 1.6723x; 1.3697x over previous
#include <cuda_runtime.h>
#include <mma.h>
#include <math.h>
#include <cstdint>

using namespace nvcuda;

// ---------------- problem constants ----------------
#define Bb   8
#define Ss   920
#define Dd   1536
#define Hh   4
#define HDd  384
#define Ll   1839          // 2*920-1
#define BH   32            // Bb*Hh
#define MQ   (BH*Ss)       // 29440
#define HALF 919           // Ll/2

// ---------------- GEMM tiling ----------------
#define BM 128
#define BN 128
#define BK 32
#define NTHREADS 256
#define LDA 36             // BK + 4 skew
#define LDN 132            // BN + 4 skew

// ---------------- scratch (static device globals; no cudaMalloc allowed) ----
__device__ float g_q[BH * Ss * HDd];           // (b,h,s,d), scaled, tf32-rounded
__device__ float g_k[BH * Ss * HDd];
__device__ float g_v[BH * Ss * HDd];
__device__ float g_r[54140160];                // MQ * Ll : R[m,l] = Q[m]·de[l]
__device__ float g_s[27084800];                // MQ * Ss : scores / probs (tf32 after softmax)
__device__ float g_hs[Bb * Ss * Dd];           // tf32-rounded hidden_states
__device__ float g_w[3 * Dd * Hh * HDd];       // tf32-rounded wq|wk|wv
__device__ float g_de[Ll * HDd];               // tf32-rounded distance_embedding

// 16-byte cp.async with zero-fill when pred==false
__device__ __forceinline__ void cp16(float* dst, const float* src, bool pred) {
    uint32_t d = (uint32_t)__cvta_generic_to_shared(dst);
    int sz = pred ? 16 : 0;
    asm volatile("cp.async.cg.shared.global [%0], [%1], 16, %2;\n" :: "r"(d), "l"(src), "r"(sz));
}
__device__ __forceinline__ void cp_commit() { asm volatile("cp.async.commit_group;\n"); }
__device__ __forceinline__ void cp_wait0()  { asm volatile("cp.async.wait_group 0;\n"); }

__device__ __forceinline__ float rne_tf32(float x) {
    return wmma::__float_to_tf32(x);
}

// ---- round-copy: dst[i] = tf32_rne(src[i]), float4-vectorized ----
__global__ __launch_bounds__(256)
void round_copy(const float4* __restrict__ src, float4* __restrict__ dst, int n4)
{
    int i = blockIdx.x * 256 + threadIdx.x;
    int stride = gridDim.x * 256;
    for (; i < n4; i += stride) {
        float4 v = src[i];
        v.x = rne_tf32(v.x); v.y = rne_tf32(v.y);
        v.z = rne_tf32(v.z); v.w = rne_tf32(v.w);
        dst[i] = v;
    }
}

// =======================================================================
// tf32 WMMA GEMM. Inputs MUST already be tf32-rounded. 128x128x32 tiles,
// double-buffered cp.async, ONE __syncthreads per K-iteration.
// BNT=true : B is (N x K) row-major  (C = A * B^T)
// BNT=false: B is (K x N) row-major  (C = A * B)
// EPI 0: C[z*sC + m*N + n] = v*scale
// EPI 1: fused QKV: z in {0,1,2} selects weight slab & output {q,k,v};
//        head-split + tf32-round output
// EPI 2: ctx: z->(b,h): C[(b*S+m)*(H*HD) + h*HD + n] = v  (full fp32)
// =======================================================================
template<bool BNT, int EPI>
__global__ __launch_bounds__(NTHREADS)
void gemm_tf32(const float* __restrict__ A,
               const float* __restrict__ Bm,
               float* __restrict__ C,
               int M, int N, int K,
               long long strA, long long strB, long long strC,
               float scale,
               float* __restrict__ C1, float* __restrict__ C2)
{
    extern __shared__ float sm[];
    float* shA = sm;                        // [2][BM*LDA]
    float* shB = sm + 2 * BM * LDA;         // NT: [2][BN*LDA]  NN: [2][BK*LDN]

    const int z = blockIdx.z;
    A += (long long)z * strA;
    if (EPI == 1) {
        Bm += (long long)z * strB;          // weight slab z
        if (z == 1)      { C = C1; }
        else if (z == 2) { C = C2; }
        if (z != 0) scale = 1.0f;
    } else {
        Bm += (long long)z * strB;
    }

    const int tid  = threadIdx.x;
    const int warp = tid >> 5;
    const int wm   = warp >> 2;    // 0..1  (64 rows)
    const int wn   = warp & 3;     // 0..3  (32 cols)

    const int m0 = blockIdx.y * BM;
    const int n0 = blockIdx.x * BN;

    const int nIter = (K + BK - 1) / BK;
    const int bStageSz = BNT ? (BN * LDA) : (BK * LDN);

    wmma::fragment<wmma::accumulator, 16, 16, 8, float> acc[4][2];
    #pragma unroll
    for (int i = 0; i < 4; i++)
        #pragma unroll
        for (int j = 0; j < 2; j++)
            wmma::fill_fragment(acc[i][j], 0.0f);

    auto issue_stage = [&](int k0, int buf) {
        float* dA = shA + buf * (BM * LDA);
        float* dB = shB + buf * bStageSz;
        // A tile: BM x BK = 128x32 floats = 1024 16B-chunks
        #pragma unroll
        for (int t = 0; t < 4; t++) {
            int idx = tid + t * NTHREADS;
            int r = idx >> 3, ch = idx & 7;
            int gm = m0 + r, gk = k0 + ch * 4;
            bool p = (gm < M) && (gk < K);
            const float* src = A + (long long)(p ? gm : 0) * K + (p ? gk : 0);
            cp16(&dA[r * LDA + ch * 4], src, p);
        }
        if (BNT) {
            #pragma unroll
            for (int t = 0; t < 4; t++) {
                int idx = tid + t * NTHREADS;
                int r = idx >> 3, ch = idx & 7;
                int gn = n0 + r, gk = k0 + ch * 4;
                bool p = (gn < N) && (gk < K);
                const float* src = Bm + (long long)(p ? gn : 0) * K + (p ? gk : 0);
                cp16(&dB[r * LDA + ch * 4], src, p);
            }
        } else {
            #pragma unroll
            for (int t = 0; t < 4; t++) {
                int idx = tid + t * NTHREADS;
                int r = idx >> 5, ch = idx & 31;
                int gk = k0 + r, gn = n0 + ch * 4;
                bool p = (gk < K) && (gn < N);
                const float* src = Bm + (long long)(p ? gk : 0) * N + (p ? gn : 0);
                cp16(&dB[r * LDN + ch * 4], src, p);
            }
        }
        cp_commit();
    };

    issue_stage(0, 0);

    for (int it = 0; it < nIter; ++it) {
        const int buf = it & 1;
        float* cA = shA + buf * (BM * LDA);
        float* cB = shB + buf * bStageSz;

        cp_wait0();
        __syncthreads();               // stage 'buf' ready; all reads of buf^1 done

        if (it + 1 < nIter) issue_stage((it + 1) * BK, buf ^ 1);

        #pragma unroll
        for (int kk = 0; kk < BK; kk += 8) {
            wmma::fragment<wmma::matrix_a, 16, 16, 8, wmma::precision::tf32, wmma::row_major> af[4];
            #pragma unroll
            for (int i = 0; i < 4; i++)
                wmma::load_matrix_sync(af[i], &cA[(wm * 64 + i * 16) * LDA + kk], LDA);
            if (BNT) {
                wmma::fragment<wmma::matrix_b, 16, 16, 8, wmma::precision::tf32, wmma::col_major> bf[2];
                #pragma unroll
                for (int j = 0; j < 2; j++)
                    wmma::load_matrix_sync(bf[j], &cB[(wn * 32 + j * 16) * LDA + kk], LDA);
                #pragma unroll
                for (int i = 0; i < 4; i++)
                    #pragma unroll
                    for (int j = 0; j < 2; j++)
                        wmma::mma_sync(acc[i][j], af[i], bf[j], acc[i][j]);
            } else {
                wmma::fragment<wmma::matrix_b, 16, 16, 8, wmma::precision::tf32, wmma::row_major> bf[2];
                #pragma unroll
                for (int j = 0; j < 2; j++)
                    wmma::load_matrix_sync(bf[j], &cB[kk * LDN + wn * 32 + j * 16], LDN);
                #pragma unroll
                for (int i = 0; i < 4; i++)
                    #pragma unroll
                    for (int j = 0; j < 2; j++)
                        wmma::mma_sync(acc[i][j], af[i], bf[j], acc[i][j]);
            }
        }
    }
    __syncthreads();

    // ---- stage C in shared, then mapped write ----
    float* shC = sm;   // [BM][LDN]
    #pragma unroll
    for (int i = 0; i < 4; i++)
        #pragma unroll
        for (int j = 0; j < 2; j++)
            wmma::store_matrix_sync(&shC[(wm * 64 + i * 16) * LDN + (wn * 32 + j * 16)],
                                    acc[i][j], LDN, wmma::mem_row_major);
    __syncthreads();

    #pragma unroll 4
    for (int e = tid; e < BM * BN; e += NTHREADS) {
        int i = e >> 7, j = e & 127;
        int gm = m0 + i, gn = n0 + j;
        if (gm >= M || gn >= N) continue;
        float v = shC[i * LDN + j] * scale;
        if (EPI == 0) {
            C[(long long)z * strC + (long long)gm * N + gn] = v;
        } else if (EPI == 1) {
            int b = gm / Ss, s = gm - b * Ss;
            int h = gn / HDd, d = gn - h * HDd;
            C[(((long long)(b * Hh + h)) * Ss + s) * HDd + d] = rne_tf32(v);
        } else { // EPI == 2
            int b = z >> 2, h = z & 3;
            C[((long long)b * Ss + gm) * (Hh * HDd) + h * HDd + gn] = v;
        }
    }
}

// =======================================================================
// bias + softmax:  scores[r,k] += R[r, k - q + 919], row softmax,
// output tf32-rounded (feeds the P@V GEMM).
// =======================================================================
__global__ __launch_bounds__(256)
void bias_softmax(float* __restrict__ sc, const float* __restrict__ R)
{
    const int r = blockIdx.x;          // 0 .. MQ-1
    const int q = r % Ss;
    float* row = sc + (long long)r * Ss;
    const float* rrow = R + (long long)r * Ll + (HALF - q);

    const int tid  = threadIdx.x;
    const int lane = tid & 31;
    const int wid  = tid >> 5;
    __shared__ float wred[8];

    float vals[4];
    float mx = -1e30f;
    #pragma unroll
    for (int i = 0; i < 4; i++) {
        int k = tid + i * 256;
        float v = -1e30f;
        if (k < Ss) v = row[k] + rrow[k];
        vals[i] = v;
        mx = fmaxf(mx, v);
    }
    #pragma unroll
    for (int o = 16; o > 0; o >>= 1) mx = fmaxf(mx, __shfl_xor_sync(0xffffffffu, mx, o));
    if (lane == 0) wred[wid] = mx;
    __syncthreads();
    mx = wred[0];
    #pragma unroll
    for (int w = 1; w < 8; w++) mx = fmaxf(mx, wred[w]);
    __syncthreads();

    float sum = 0.0f;
    #pragma unroll
    for (int i = 0; i < 4; i++) {
        int k = tid + i * 256;
        float e = 0.0f;
        if (k < Ss) e = __expf(vals[i] - mx);
        vals[i] = e;
        sum += e;
    }
    #pragma unroll
    for (int o = 16; o > 0; o >>= 1) sum += __shfl_xor_sync(0xffffffffu, sum, o);
    if (lane == 0) wred[wid] = sum;
    __syncthreads();
    sum = 0.0f;
    #pragma unroll
    for (int w = 0; w < 8; w++) sum += wred[w];

    const float inv = 1.0f / sum;
    #pragma unroll
    for (int i = 0; i < 4; i++) {
        int k = tid + i * 256;
        if (k < Ss) row[k] = rne_tf32(vals[i] * inv);
    }
}

// =======================================================================
extern "C" void kernel_launch(void* const* d_in, const int* in_sizes, int n_in,
                              void* d_out, int out_size)
{
    (void)in_sizes; (void)n_in; (void)out_size;
    const float* hs = (const float*)d_in[0];
    const float* wq = (const float*)d_in[1];
    const float* wk = (const float*)d_in[2];
    const float* wv = (const float*)d_in[3];
    const float* de = (const float*)d_in[4];
    float* out = (float*)d_out;

    float *q, *k, *v, *r, *s, *hsr, *w, *der;
    cudaGetSymbolAddress((void**)&q,   g_q);
    cudaGetSymbolAddress((void**)&k,   g_k);
    cudaGetSymbolAddress((void**)&v,   g_v);
    cudaGetSymbolAddress((void**)&r,   g_r);
    cudaGetSymbolAddress((void**)&s,   g_s);
    cudaGetSymbolAddress((void**)&hsr, g_hs);
    cudaGetSymbolAddress((void**)&w,   g_w);
    cudaGetSymbolAddress((void**)&der, g_de);

    const int smemNT = 4 * BM * LDA * (int)sizeof(float);            // 73728
    const int smemNN = (2 * BM * LDA + 2 * BK * LDN) * (int)sizeof(float);
    const int smemC  = BM * LDN * (int)sizeof(float);
    const int smem   = smemNT > smemNN ? (smemNT > smemC ? smemNT : smemC)
                                       : (smemNN > smemC ? smemNN : smemC);
    cudaFuncSetAttribute(gemm_tf32<false, 1>, cudaFuncAttributeMaxDynamicSharedMemorySize, smem);
    cudaFuncSetAttribute(gemm_tf32<true,  0>, cudaFuncAttributeMaxDynamicSharedMemorySize, smem);
    cudaFuncSetAttribute(gemm_tf32<false, 2>, cudaFuncAttributeMaxDynamicSharedMemorySize, smem);

    const float inv = 1.0f / sqrtf((float)HDd);
    dim3 blk(NTHREADS);

    // 0) tf32 pre-rounding of raw inputs (RNE), float4-vectorized
    const int WN = Dd * Hh * HDd;   // 2359296 per weight
    round_copy<<<512, 256>>>((const float4*)hs, (float4*)hsr, (Bb * Ss * Dd) / 4);
    round_copy<<<256, 256>>>((const float4*)wq, (float4*)(w), WN / 4);
    round_copy<<<256, 256>>>((const float4*)wk, (float4*)(w + WN), WN / 4);
    round_copy<<<256, 256>>>((const float4*)wv, (float4*)(w + 2 * WN), WN / 4);
    round_copy<<<128, 256>>>((const float4*)de, (float4*)der, (Ll * HDd) / 4);

    // 1) fused QKV: X(7360x1536) @ {Wq,Wk,Wv}, head-split + tf32-rounded out
    dim3 gA((Hh * HDd + BN - 1) / BN, (Bb * Ss + BM - 1) / BM, 3);   // (12, 58, 3)
    gemm_tf32<false, 1><<<gA, blk, smem>>>(hsr, w, q, Bb * Ss, Hh * HDd, Dd,
                                           0, (long long)WN, 0, inv, k, v);

    // 2) R = Q @ DE^T : (29440 x 1839), K = 384
    dim3 gR((Ll + BN - 1) / BN, (MQ + BM - 1) / BM, 1);              // (15, 230)
    gemm_tf32<true, 0><<<gR, blk, smem>>>(q, der, r, MQ, Ll, HDd, 0, 0, 0, 1.0f,
                                          nullptr, nullptr);

    // 3) scores = Q @ K^T per (b,h): 32 x (920 x 920), K = 384
    dim3 gS((Ss + BN - 1) / BN, (Ss + BM - 1) / BM, BH);             // (8, 8, 32)
    gemm_tf32<true, 0><<<gS, blk, smem>>>(q, k, s, Ss, Ss, HDd,
                                          (long long)Ss * HDd, (long long)Ss * HDd,
                                          (long long)Ss * Ss, 1.0f,
                                          nullptr, nullptr);

    // 4) bias add (rotated rel-pos) + row softmax (tf32-rounded probs)
    bias_softmax<<<MQ, 256>>>(s, r);

    // 5) ctx = P @ V per (b,h) -> (B, S, H*HD) output
    dim3 gO((HDd + BN - 1) / BN, (Ss + BM - 1) / BM, BH);            // (3, 8, 32)
    gemm_tf32<false, 2><<<gO, blk, smem>>>(s, v, out, Ss, HDd, Ss,
                                           (long long)Ss * Ss, (long long)Ss * HDd,
                                           0, 1.0f,
                                           nullptr, nullptr);
}

// round 6
// speedup vs baseline: 5.2883x; 3.1623x over previous
#include <cuda_runtime.h>
#include <cuda_fp16.h>
#include <mma.h>
#include <math.h>
#include <cstdint>

using namespace nvcuda;

// ---------------- problem constants ----------------
#define Bb   8
#define Ss   920
#define Dd   1536
#define Hh   4
#define HDd  384
#define Ll   1839
#define BH   32
#define MQ   29440
#define HALF 919
#define RSTRIDE 1840
#define WN3  (Dd*Hh*HDd)          // 2359296 per weight matrix

// ---------------- GEMM tiling ----------------
#define BM 128
#define TK 32                     // k-depth per stage (halfs)
#define NTHREADS 256
#define LDA 40                    // TK + 8 skew (halfs); 80B row stride

// ---------------- scratch ----------------
__device__ __half g_q[BH * Ss * HDd];
__device__ __half g_k[BH * Ss * HDd];
__device__ __half g_vt[BH * HDd * Ss];           // V^T: [bh][d][s]
__device__ float  g_r[(long long)MQ * RSTRIDE];  // rel bias, fp32
__device__ float  g_s[(long long)BH * Ss * Ss];  // scores fp32
__device__ __half g_p[(long long)BH * Ss * Ss];  // probs half
__device__ __half g_hs[Bb * Ss * Dd];
__device__ __half g_wt[3 * WN3];                 // W^T half
__device__ __half g_de[Ll * HDd];

// ---------------- helpers ----------------
__device__ __forceinline__ uint32_t smem_u32(const void* p) {
    uint32_t a;
    asm("{ .reg .u64 t; cvta.to.shared.u64 t, %1; cvt.u32.u64 %0, t; }" : "=r"(a) : "l"(p));
    return a;
}
__device__ __forceinline__ void cp16s(uint32_t dst, const void* src, bool p) {
    int sz = p ? 16 : 0;
    asm volatile("cp.async.cg.shared.global [%0], [%1], 16, %2;\n" :: "r"(dst), "l"(src), "r"(sz));
}
__device__ __forceinline__ void cp_commit() { asm volatile("cp.async.commit_group;\n"); }
__device__ __forceinline__ void cp_wait0()  { asm volatile("cp.async.wait_group 0;\n"); }

// ---------------- prep kernels ----------------
__global__ __launch_bounds__(256)
void f2h_copy(const float4* __restrict__ src, uint2* __restrict__ dst, int n4)
{
    int i = blockIdx.x * 256 + threadIdx.x;
    int st = gridDim.x * 256;
    for (; i < n4; i += st) {
        float4 v = src[i];
        __half2 h01 = __floats2half2_rn(v.x, v.y);
        __half2 h23 = __floats2half2_rn(v.z, v.w);
        uint2 o;
        o.x = *reinterpret_cast<uint32_t*>(&h01);
        o.y = *reinterpret_cast<uint32_t*>(&h23);
        dst[i] = o;
    }
}

// W (1536x1536) -> W^T half. grid (48,48), block (32,8)
__global__ __launch_bounds__(256)
void transpose_h(const float* __restrict__ src, __half* __restrict__ dst)
{
    __shared__ float t[32][33];
    int tx = threadIdx.x, ty = threadIdx.y;
    int x = blockIdx.x * 32 + tx;
    int y0 = blockIdx.y * 32;
    #pragma unroll
    for (int i = 0; i < 32; i += 8)
        t[ty + i][tx] = src[(long long)(y0 + ty + i) * 1536 + x];
    __syncthreads();
    int x2 = blockIdx.y * 32 + tx;
    int y2 = blockIdx.x * 32;
    #pragma unroll
    for (int i = 0; i < 32; i += 8)
        dst[(long long)(y2 + ty + i) * 1536 + x2] = __float2half_rn(t[tx][ty + i]);
}

// =======================================================================
// fp16 WMMA NT GEMM: C = A(MxK,row,half) * B(NxK,row,half)^T, fp32 accum.
// CTA tile BM x BNv, 8 warps (2 x 4), warp tile 64 x (BNv/4).
// 2-stage cp.async pipeline, TK=32 per stage.
// EPI 0: fp32 C[z*strC + gm*ldC + gn] = v*scale
// EPI 1: fused QKV (z: 0->Cv(q),1->C1(k),2->C2(vt)); scale only for z==0
// EPI 2: ctx: z=(b,h): fp32 out[(b*S+gm)*1536 + h*384 + gn] = v
// =======================================================================
template<int BNv, int EPI>
__global__ __launch_bounds__(NTHREADS)
void gemm_h(const __half* __restrict__ A, const __half* __restrict__ B,
            void* __restrict__ Cv,
            int M, int N, int K,
            long long strA, long long strB, long long strC, int ldC,
            float scale, __half* __restrict__ C1, __half* __restrict__ C2)
{
    constexpr int WNv = BNv / 4;          // warp n-width (64 or 32)
    constexpr int NF  = WNv / 16;         // B frags per warp (4 or 2)
    constexpr int A_BYTES = BM * LDA * 2;
    constexpr int B_BYTES = BNv * LDA * 2;
    constexpr int STAGE_BYTES = A_BYTES + B_BYTES;
    constexpr int LDC = BNv + 4;

    extern __shared__ char smem[];
    const uint32_t sb = smem_u32(smem);

    const int tid  = threadIdx.x;
    const int warp = tid >> 5;
    const int wm   = warp >> 2;           // 0..1
    const int wn   = warp & 3;            // 0..3
    const int z    = blockIdx.z;

    A += (long long)z * strA;
    B += (long long)z * strB;
    if (EPI == 1 && z != 0) scale = 1.0f;   // only Q gets 1/sqrt(HD)

    const int m0 = blockIdx.y * BM;
    const int n0 = blockIdx.x * BNv;
    const int nIter = (K + TK - 1) / TK;

    wmma::fragment<wmma::accumulator, 16, 16, 16, float> acc[4][NF];
    #pragma unroll
    for (int i = 0; i < 4; i++)
        #pragma unroll
        for (int j = 0; j < NF; j++)
            wmma::fill_fragment(acc[i][j], 0.0f);

    auto issue_stage = [&](int s) {
        const uint32_t base = sb + (uint32_t)(s & 1) * STAGE_BYTES;
        const int k0 = s * TK;
        // A tile: BM x TK halfs = BM*4 16B-chunks
        #pragma unroll
        for (int t = 0; t < BM * 4 / NTHREADS; t++) {
            int idx = tid + t * NTHREADS;
            int r = idx >> 2, c = idx & 3;
            int gm = m0 + r, gk = k0 + c * 8;
            bool p = (gm < M) && (gk < K);
            const __half* src = A + (long long)(p ? gm : 0) * K + (p ? gk : 0);
            cp16s(base + (uint32_t)(r * (LDA * 2) + c * 16), src, p);
        }
        // B tile: BNv x TK halfs
        #pragma unroll
        for (int t = 0; t < BNv * 4 / NTHREADS; t++) {
            int idx = tid + t * NTHREADS;
            int r = idx >> 2, c = idx & 3;
            int gn = n0 + r, gk = k0 + c * 8;
            bool p = (gn < N) && (gk < K);
            const __half* src = B + (long long)(p ? gn : 0) * K + (p ? gk : 0);
            cp16s(base + (uint32_t)A_BYTES + (uint32_t)(r * (LDA * 2) + c * 16), src, p);
        }
        cp_commit();
    };

    issue_stage(0);

    for (int it = 0; it < nIter; ++it) {
        const __half* cA = (const __half*)(smem + (it & 1) * STAGE_BYTES);
        const __half* cB = (const __half*)(smem + (it & 1) * STAGE_BYTES + A_BYTES);

        cp_wait0();
        __syncthreads();
        if (it + 1 < nIter) issue_stage(it + 1);

        #pragma unroll
        for (int kk = 0; kk < TK; kk += 16) {
            wmma::fragment<wmma::matrix_a, 16, 16, 16, __half, wmma::row_major> af[4];
            #pragma unroll
            for (int i = 0; i < 4; i++)
                wmma::load_matrix_sync(af[i], cA + (wm * 64 + i * 16) * LDA + kk, LDA);
            wmma::fragment<wmma::matrix_b, 16, 16, 16, __half, wmma::col_major> bf[NF];
            #pragma unroll
            for (int j = 0; j < NF; j++)
                wmma::load_matrix_sync(bf[j], cB + (wn * WNv + j * 16) * LDA + kk, LDA);
            #pragma unroll
            for (int i = 0; i < 4; i++)
                #pragma unroll
                for (int j = 0; j < NF; j++)
                    wmma::mma_sync(acc[i][j], af[i], bf[j], acc[i][j]);
        }
    }
    __syncthreads();

    // ---- stage C (fp32) in smem, then mapped writes ----
    float* shC = (float*)smem;   // [BM][LDC]
    #pragma unroll
    for (int i = 0; i < 4; i++)
        #pragma unroll
        for (int j = 0; j < NF; j++)
            wmma::store_matrix_sync(&shC[(wm * 64 + i * 16) * LDC + (wn * WNv + j * 16)],
                                    acc[i][j], LDC, wmma::mem_row_major);
    __syncthreads();

    if (EPI == 1 && z == 2) {
        // V^T into C2: iterate m fast for coalesced s-dim stores
        #pragma unroll 4
        for (int idx = tid; idx < BM * BNv; idx += NTHREADS) {
            int i = idx & (BM - 1), j = idx >> 7;
            int gm = m0 + i, gn = n0 + j;
            if (gm >= M || gn >= N) continue;
            float v = shC[i * LDC + j];
            int b2 = gm / Ss, sP = gm - b2 * Ss;
            int h = gn / HDd, d = gn - h * HDd;
            C2[(((long long)(b2 * Hh + h)) * HDd + d) * Ss + sP] = __float2half_rn(v);
        }
    } else {
        #pragma unroll 4
        for (int idx = tid; idx < BM * BNv; idx += NTHREADS) {
            int i = idx / BNv, j = idx % BNv;
            int gm = m0 + i, gn = n0 + j;
            if (gm >= M || gn >= N) continue;
            float v = shC[i * LDC + j] * scale;
            if (EPI == 0) {
                ((float*)Cv)[(long long)z * strC + (long long)gm * ldC + gn] = v;
            } else if (EPI == 1) {
                int b2 = gm / Ss, sP = gm - b2 * Ss;
                int h = gn / HDd, d = gn - h * HDd;
                __half hv = __float2half_rn(v);
                long long o = (((long long)(b2 * Hh + h)) * Ss + sP) * HDd + d;
                if (z == 0) ((__half*)Cv)[o] = hv; else C1[o] = hv;
            } else {
                int b2 = z >> 2, h = z & 3;
                ((float*)Cv)[((long long)b2 * Ss + gm) * (Hh * HDd) + h * HDd + gn] = v;
            }
        }
    }
}

// =======================================================================
// bias + softmax: scores[r,k] += R[r, k-q+919]; row softmax; half probs out
// =======================================================================
__global__ __launch_bounds__(256)
void bias_softmax(const float* __restrict__ sc, const float* __restrict__ R,
                  __half* __restrict__ P)
{
    const int r = blockIdx.x;
    const int q = r % Ss;
    const float* row = sc + (long long)r * Ss;
    const float* rrow = R + (long long)r * RSTRIDE + (HALF - q);
    __half* prow = P + (long long)r * Ss;

    const int tid = threadIdx.x, lane = tid & 31, wid = tid >> 5;
    __shared__ float wred[8];

    float vals[4];
    float mx = -1e30f;
    #pragma unroll
    for (int i = 0; i < 4; i++) {
        int k = tid + i * 256;
        float v = -1e30f;
        if (k < Ss) v = row[k] + rrow[k];
        vals[i] = v;
        mx = fmaxf(mx, v);
    }
    #pragma unroll
    for (int o = 16; o > 0; o >>= 1) mx = fmaxf(mx, __shfl_xor_sync(0xffffffffu, mx, o));
    if (lane == 0) wred[wid] = mx;
    __syncthreads();
    mx = wred[0];
    #pragma unroll
    for (int w = 1; w < 8; w++) mx = fmaxf(mx, wred[w]);
    __syncthreads();

    float sum = 0.0f;
    #pragma unroll
    for (int i = 0; i < 4; i++) {
        int k = tid + i * 256;
        float e = 0.0f;
        if (k < Ss) e = __expf(vals[i] - mx);
        vals[i] = e;
        sum += e;
    }
    #pragma unroll
    for (int o = 16; o > 0; o >>= 1) sum += __shfl_xor_sync(0xffffffffu, sum, o);
    if (lane == 0) wred[wid] = sum;
    __syncthreads();
    sum = 0.0f;
    #pragma unroll
    for (int w = 0; w < 8; w++) sum += wred[w];

    const float inv = 1.0f / sum;
    #pragma unroll
    for (int i = 0; i < 4; i++) {
        int k = tid + i * 256;
        if (k < Ss) prow[k] = __float2half_rn(vals[i] * inv);
    }
}

// =======================================================================
extern "C" void kernel_launch(void* const* d_in, const int* in_sizes, int n_in,
                              void* d_out, int out_size)
{
    (void)in_sizes; (void)n_in; (void)out_size;
    const float* hs = (const float*)d_in[0];
    const float* wq = (const float*)d_in[1];
    const float* wk = (const float*)d_in[2];
    const float* wv = (const float*)d_in[3];
    const float* de = (const float*)d_in[4];
    float* out = (float*)d_out;

    __half *q, *k, *vt, *p, *hsr, *wt, *der;
    float *r, *s;
    cudaGetSymbolAddress((void**)&q,   g_q);
    cudaGetSymbolAddress((void**)&k,   g_k);
    cudaGetSymbolAddress((void**)&vt,  g_vt);
    cudaGetSymbolAddress((void**)&r,   g_r);
    cudaGetSymbolAddress((void**)&s,   g_s);
    cudaGetSymbolAddress((void**)&p,   g_p);
    cudaGetSymbolAddress((void**)&hsr, g_hs);
    cudaGetSymbolAddress((void**)&wt,  g_wt);
    cudaGetSymbolAddress((void**)&der, g_de);

    // smem: max(2 stages, shC)
    const int smem256 = (BM * (256 + 4)) * 4;                       // 133120
    const int smem128 = (BM * (128 + 4)) * 4;                       // 67584
    cudaFuncSetAttribute(gemm_h<256, 0>, cudaFuncAttributeMaxDynamicSharedMemorySize, smem256);
    cudaFuncSetAttribute(gemm_h<256, 1>, cudaFuncAttributeMaxDynamicSharedMemorySize, smem256);
    cudaFuncSetAttribute(gemm_h<128, 2>, cudaFuncAttributeMaxDynamicSharedMemorySize, smem128);

    const float inv = 1.0f / sqrtf((float)HDd);
    dim3 blk(NTHREADS);

    // 0) prep: fp32 -> half (RNE); W transposed
    f2h_copy<<<512, 256>>>((const float4*)hs, (uint2*)hsr, (Bb * Ss * Dd) / 4);
    f2h_copy<<<128, 256>>>((const float4*)de, (uint2*)der, (Ll * HDd) / 4);
    {
        dim3 b(32, 8);
        transpose_h<<<dim3(48, 48), b>>>(wq, wt);
        transpose_h<<<dim3(48, 48), b>>>(wk, wt + WN3);
        transpose_h<<<dim3(48, 48), b>>>(wv, wt + 2 * WN3);
    }

    // 1) fused QKV: hs(7360x1536) @ W^T -> q,k half (b,h,s,d) + vt half (b,h,d,s)
    dim3 gA(Dd / 256, (Bb * Ss + BM - 1) / BM, 3);                  // (6, 58, 3)
    gemm_h<256, 1><<<gA, blk, smem256>>>(hsr, wt, q, Bb * Ss, Hh * HDd, Dd,
                                         0, (long long)WN3, 0, 0, inv, k, vt);

    // 2) R = Q @ DE^T : (29440 x 1839), K=384 -> fp32, padded stride
    dim3 gR((Ll + 255) / 256, MQ / BM, 1);                          // (8, 230)
    gemm_h<256, 0><<<gR, blk, smem256>>>(q, der, r, MQ, Ll, HDd,
                                         0, 0, 0, RSTRIDE, 1.0f, nullptr, nullptr);

    // 3) scores = Q @ K^T per bh: 32 x (920x920), K=384 -> fp32
    dim3 gS((Ss + 255) / 256, (Ss + BM - 1) / BM, BH);              // (4, 8, 32)
    gemm_h<256, 0><<<gS, blk, smem256>>>(q, k, s, Ss, Ss, HDd,
                                         (long long)Ss * HDd, (long long)Ss * HDd,
                                         (long long)Ss * Ss, Ss, 1.0f, nullptr, nullptr);

    // 4) bias + softmax -> half probs
    bias_softmax<<<MQ, 256>>>(s, r, p);

    // 5) ctx = P @ Vt^T per bh -> fp32 (B,S,H*HD)
    dim3 gO(HDd / 128, (Ss + BM - 1) / BM, BH);                     // (3, 8, 32)
    gemm_h<128, 2><<<gO, blk, smem128>>>(p, vt, out, Ss, HDd, Ss,
                                         (long long)Ss * Ss, (long long)HDd * Ss,
                                         0, 0, 1.0f, nullptr, nullptr);
}

// round 7
// speedup vs baseline: 6.5457x; 1.2378x over previous
#include <cuda_runtime.h>
#include <cuda_fp16.h>
#include <mma.h>
#include <math.h>
#include <cstdint>

using namespace nvcuda;

// ---------------- problem constants ----------------
#define Bb   8
#define Ss   920
#define Dd   1536
#define Hh   4
#define HDd  384
#define Ll   1839
#define BH   32
#define MQ   29440
#define HALFL 919
#define RST  2048                 // padded R row stride (fp32)
#define SROW 1024                 // padded scores row stride (fp32)
#define SZSTR (1024*1024)         // padded scores per-bh slab (1024 rows x 1024 cols)
#define WN3  (Dd*Hh*HDd)          // 2359296 per weight matrix

// ---------------- GEMM tiling ----------------
#define BM 128
#define TK 64                     // k-depth per stage (halfs)
#define NSTAGE 3
#define NTHREADS 256
#define LDA 72                    // TK + 8 skew (halfs); 144B row stride

// ---------------- scratch ----------------
__device__ __half g_q[BH * Ss * HDd];
__device__ __half g_k[BH * Ss * HDd];
__device__ __half g_vt[BH * HDd * Ss];            // V^T: [bh][d][s]
__device__ float  g_r[(long long)MQ * RST];       // rel bias, fp32, padded
__device__ float  g_s[(long long)BH * SZSTR];     // scores fp32, padded slabs
__device__ __half g_p[(long long)BH * Ss * Ss];   // probs half, packed
__device__ __half g_hs[Bb * Ss * Dd];
__device__ __half g_wt[3 * WN3];                  // W^T half
__device__ __half g_de[Ll * HDd];

// ---------------- helpers ----------------
__device__ __forceinline__ uint32_t smem_u32(const void* p) {
    uint32_t a;
    asm("{ .reg .u64 t; cvta.to.shared.u64 t, %1; cvt.u32.u64 %0, t; }" : "=r"(a) : "l"(p));
    return a;
}
__device__ __forceinline__ void cp16s(uint32_t dst, const void* src, bool p) {
    int sz = p ? 16 : 0;
    asm volatile("cp.async.cg.shared.global [%0], [%1], 16, %2;\n" :: "r"(dst), "l"(src), "r"(sz));
}
__device__ __forceinline__ void cp_commit() { asm volatile("cp.async.commit_group;\n"); }
__device__ __forceinline__ void cp_wait0()  { asm volatile("cp.async.wait_group 0;\n"); }
__device__ __forceinline__ void cp_wait1()  { asm volatile("cp.async.wait_group 1;\n"); }

// ---------------- prep kernels ----------------
__global__ __launch_bounds__(256)
void f2h_copy(const float4* __restrict__ src, uint2* __restrict__ dst, int n4)
{
    int i = blockIdx.x * 256 + threadIdx.x;
    int st = gridDim.x * 256;
    for (; i < n4; i += st) {
        float4 v = src[i];
        __half2 h01 = __floats2half2_rn(v.x, v.y);
        __half2 h23 = __floats2half2_rn(v.z, v.w);
        uint2 o;
        o.x = *reinterpret_cast<uint32_t*>(&h01);
        o.y = *reinterpret_cast<uint32_t*>(&h23);
        dst[i] = o;
    }
}

// W (1536x1536) -> W^T half. grid (48,48), block (32,8)
__global__ __launch_bounds__(256)
void transpose_h(const float* __restrict__ src, __half* __restrict__ dst)
{
    __shared__ float t[32][33];
    int tx = threadIdx.x, ty = threadIdx.y;
    int x = blockIdx.x * 32 + tx;
    int y0 = blockIdx.y * 32;
    #pragma unroll
    for (int i = 0; i < 32; i += 8)
        t[ty + i][tx] = src[(long long)(y0 + ty + i) * 1536 + x];
    __syncthreads();
    int x2 = blockIdx.y * 32 + tx;
    int y2 = blockIdx.x * 32;
    #pragma unroll
    for (int i = 0; i < 32; i += 8)
        dst[(long long)(y2 + ty + i) * 1536 + x2] = __float2half_rn(t[tx][ty + i]);
}

// =======================================================================
// fp16 WMMA NT GEMM: C = A(MxK,row,half) * B(NxK,row,half)^T, fp32 accum.
// CTA tile BM x BNv, 8 warps (2x4), warp tile 64 x (BNv/4).
// 3-stage cp.async pipeline, TK=64 per stage, wait_group 1.
// EPI 0: fp32 direct store_matrix_sync to C[z*strC + gm*ldC + gn] (no scale)
// EPI 1: fused QKV (z: 0->Cv(q),1->C1(k),2->C2(vt)); scale only for z==0
// EPI 2: ctx: z=(b,h): fp32 out[(b*S+gm)*1536 + h*384 + gn] = v
// BAND: early-exit for R band (only columns l in [919-qhi, 1838-qlo] used)
// =======================================================================
template<int BNv, int EPI, bool BAND>
__global__ __launch_bounds__(NTHREADS)
void gemm_h(const __half* __restrict__ A, const __half* __restrict__ B,
            void* __restrict__ Cv,
            int M, int N, int K,
            long long strA, long long strB, long long strC, int ldC,
            float scale, __half* __restrict__ C1, __half* __restrict__ C2)
{
    constexpr int WNv = BNv / 4;          // warp n-width (64 or 32)
    constexpr int NF  = WNv / 16;         // B frags per warp (4 or 2)
    constexpr int A_BYTES = BM * LDA * 2;
    constexpr int B_BYTES = BNv * LDA * 2;
    constexpr int STAGE_BYTES = A_BYTES + B_BYTES;
    constexpr int LDC = BNv + 4;

    const int m0 = blockIdx.y * BM;
    const int n0 = blockIdx.x * BNv;

    if (BAND) {
        // rows m0..m0+127 -> q = m % 920; used l-window union
        int mq0 = m0 % Ss;
        int qlo, qhi;
        if (mq0 + (BM - 1) < Ss) { qlo = mq0; qhi = mq0 + BM - 1; }
        else                     { qlo = 0;   qhi = Ss - 1; }
        int lmin = HALFL - qhi, lmax = (Ll - 1) - qlo;
        if (n0 > lmax || n0 + BNv - 1 < lmin) return;
    }

    extern __shared__ char smem[];
    const uint32_t sb = smem_u32(smem);

    const int tid  = threadIdx.x;
    const int warp = tid >> 5;
    const int wm   = warp >> 2;           // 0..1
    const int wn   = warp & 3;            // 0..3
    const int z    = blockIdx.z;

    A += (long long)z * strA;
    B += (long long)z * strB;
    if (EPI == 1 && z != 0) scale = 1.0f;   // only Q gets 1/sqrt(HD)

    const int nIter = (K + TK - 1) / TK;

    wmma::fragment<wmma::accumulator, 16, 16, 16, float> acc[4][NF];
    #pragma unroll
    for (int i = 0; i < 4; i++)
        #pragma unroll
        for (int j = 0; j < NF; j++)
            wmma::fill_fragment(acc[i][j], 0.0f);

    auto issue_stage = [&](int s) {
        const uint32_t base = sb + (uint32_t)(s % NSTAGE) * STAGE_BYTES;
        const int k0 = s * TK;
        // A tile: BM x TK halfs = BM*8 16B-chunks
        #pragma unroll
        for (int t = 0; t < BM * 8 / NTHREADS; t++) {
            int idx = tid + t * NTHREADS;
            int r = idx >> 3, c = idx & 7;
            int gm = m0 + r, gk = k0 + c * 8;
            bool p = (gm < M) && (gk < K);
            const __half* src = A + (long long)(p ? gm : 0) * K + (p ? gk : 0);
            cp16s(base + (uint32_t)(r * (LDA * 2) + c * 16), src, p);
        }
        // B tile: BNv x TK halfs
        #pragma unroll
        for (int t = 0; t < BNv * 8 / NTHREADS; t++) {
            int idx = tid + t * NTHREADS;
            int r = idx >> 3, c = idx & 7;
            int gn = n0 + r, gk = k0 + c * 8;
            bool p = (gn < N) && (gk < K);
            const __half* src = B + (long long)(p ? gn : 0) * K + (p ? gk : 0);
            cp16s(base + (uint32_t)A_BYTES + (uint32_t)(r * (LDA * 2) + c * 16), src, p);
        }
        cp_commit();
    };

    issue_stage(0);
    issue_stage(1);

    for (int it = 0; it < nIter; ++it) {
        const __half* cA = (const __half*)(smem + (it % NSTAGE) * STAGE_BYTES);
        const __half* cB = (const __half*)(smem + (it % NSTAGE) * STAGE_BYTES + A_BYTES);

        if (it + 1 < nIter) cp_wait1(); else cp_wait0();
        __syncthreads();
        if (it + 2 < nIter) issue_stage(it + 2);

        #pragma unroll
        for (int kk = 0; kk < TK; kk += 16) {
            wmma::fragment<wmma::matrix_a, 16, 16, 16, __half, wmma::row_major> af[4];
            #pragma unroll
            for (int i = 0; i < 4; i++)
                wmma::load_matrix_sync(af[i], cA + (wm * 64 + i * 16) * LDA + kk, LDA);
            wmma::fragment<wmma::matrix_b, 16, 16, 16, __half, wmma::col_major> bf[NF];
            #pragma unroll
            for (int j = 0; j < NF; j++)
                wmma::load_matrix_sync(bf[j], cB + (wn * WNv + j * 16) * LDA + kk, LDA);
            #pragma unroll
            for (int i = 0; i < 4; i++)
                #pragma unroll
                for (int j = 0; j < NF; j++)
                    wmma::mma_sync(acc[i][j], af[i], bf[j], acc[i][j]);
        }
    }

    if (EPI == 0) {
        // direct fp32 global stores (caller guarantees padded strides)
        float* Cg = (float*)Cv + (long long)z * strC;
        #pragma unroll
        for (int i = 0; i < 4; i++) {
            int gm = m0 + wm * 64 + i * 16;
            #pragma unroll
            for (int j = 0; j < NF; j++) {
                int gn = n0 + wn * WNv + j * 16;
                wmma::store_matrix_sync(Cg + (long long)gm * ldC + gn,
                                        acc[i][j], ldC, wmma::mem_row_major);
            }
        }
        return;
    }

    __syncthreads();
    // ---- stage C (fp32) in smem, then mapped writes ----
    float* shC = (float*)smem;   // [BM][LDC]
    #pragma unroll
    for (int i = 0; i < 4; i++)
        #pragma unroll
        for (int j = 0; j < NF; j++)
            wmma::store_matrix_sync(&shC[(wm * 64 + i * 16) * LDC + (wn * WNv + j * 16)],
                                    acc[i][j], LDC, wmma::mem_row_major);
    __syncthreads();

    if (EPI == 1 && z == 2) {
        // V^T into C2: iterate m fast for coalesced s-dim stores
        #pragma unroll 4
        for (int idx = tid; idx < BM * BNv; idx += NTHREADS) {
            int i = idx & (BM - 1), j = idx >> 7;
            int gm = m0 + i, gn = n0 + j;
            if (gm >= M || gn >= N) continue;
            float v = shC[i * LDC + j];
            int b2 = gm / Ss, sP = gm - b2 * Ss;
            int h = gn / HDd, d = gn - h * HDd;
            C2[(((long long)(b2 * Hh + h)) * HDd + d) * Ss + sP] = __float2half_rn(v);
        }
    } else {
        #pragma unroll 4
        for (int idx = tid; idx < BM * BNv; idx += NTHREADS) {
            int i = idx / BNv, j = idx % BNv;
            int gm = m0 + i, gn = n0 + j;
            if (gm >= M || gn >= N) continue;
            float v = shC[i * LDC + j] * scale;
            if (EPI == 1) {
                int b2 = gm / Ss, sP = gm - b2 * Ss;
                int h = gn / HDd, d = gn - h * HDd;
                __half hv = __float2half_rn(v);
                long long o = (((long long)(b2 * Hh + h)) * Ss + sP) * HDd + d;
                if (z == 0) ((__half*)Cv)[o] = hv; else C1[o] = hv;
            } else {
                int b2 = z >> 2, h = z & 3;
                ((float*)Cv)[((long long)b2 * Ss + gm) * (Hh * HDd) + h * HDd + gn] = v;
            }
        }
    }
}

// =======================================================================
// bias + softmax: scores[bh,q,k] += R[m, k-q+919]; row softmax; half probs
// padded strides: scores row SROW, slab SZSTR; R row RST; probs packed 920
// =======================================================================
__global__ __launch_bounds__(256)
void bias_softmax(const float* __restrict__ sc, const float* __restrict__ R,
                  __half* __restrict__ P)
{
    const int r = blockIdx.x;               // 0 .. MQ-1
    const int bh = r / Ss, q = r - bh * Ss;
    const float* row = sc + (long long)bh * SZSTR + (long long)q * SROW;
    const float* rrow = R + (long long)r * RST + (HALFL - q);
    __half* prow = P + (long long)r * Ss;

    const int tid = threadIdx.x, lane = tid & 31, wid = tid >> 5;
    __shared__ float wred[8];

    float vals[4];
    float mx = -1e30f;
    #pragma unroll
    for (int i = 0; i < 4; i++) {
        int k = tid + i * 256;
        float v = -1e30f;
        if (k < Ss) v = row[k] + rrow[k];
        vals[i] = v;
        mx = fmaxf(mx, v);
    }
    #pragma unroll
    for (int o = 16; o > 0; o >>= 1) mx = fmaxf(mx, __shfl_xor_sync(0xffffffffu, mx, o));
    if (lane == 0) wred[wid] = mx;
    __syncthreads();
    mx = wred[0];
    #pragma unroll
    for (int w = 1; w < 8; w++) mx = fmaxf(mx, wred[w]);
    __syncthreads();

    float sum = 0.0f;
    #pragma unroll
    for (int i = 0; i < 4; i++) {
        int k = tid + i * 256;
        float e = 0.0f;
        if (k < Ss) e = __expf(vals[i] - mx);
        vals[i] = e;
        sum += e;
    }
    #pragma unroll
    for (int o = 16; o > 0; o >>= 1) sum += __shfl_xor_sync(0xffffffffu, sum, o);
    if (lane == 0) wred[wid] = sum;
    __syncthreads();
    sum = 0.0f;
    #pragma unroll
    for (int w = 0; w < 8; w++) sum += wred[w];

    const float inv = 1.0f / sum;
    #pragma unroll
    for (int i = 0; i < 4; i++) {
        int k = tid + i * 256;
        if (k < Ss) prow[k] = __float2half_rn(vals[i] * inv);
    }
}

// =======================================================================
extern "C" void kernel_launch(void* const* d_in, const int* in_sizes, int n_in,
                              void* d_out, int out_size)
{
    (void)in_sizes; (void)n_in; (void)out_size;
    const float* hs = (const float*)d_in[0];
    const float* wq = (const float*)d_in[1];
    const float* wk = (const float*)d_in[2];
    const float* wv = (const float*)d_in[3];
    const float* de = (const float*)d_in[4];
    float* out = (float*)d_out;

    __half *q, *k, *vt, *p, *hsr, *wt, *der;
    float *r, *s;
    cudaGetSymbolAddress((void**)&q,   g_q);
    cudaGetSymbolAddress((void**)&k,   g_k);
    cudaGetSymbolAddress((void**)&vt,  g_vt);
    cudaGetSymbolAddress((void**)&r,   g_r);
    cudaGetSymbolAddress((void**)&s,   g_s);
    cudaGetSymbolAddress((void**)&p,   g_p);
    cudaGetSymbolAddress((void**)&hsr, g_hs);
    cudaGetSymbolAddress((void**)&wt,  g_wt);
    cudaGetSymbolAddress((void**)&der, g_de);

    // smem requirements
    const int stage256 = (BM * LDA * 2) + (256 * LDA * 2);          // 55296
    const int stage128 = (BM * LDA * 2) + (128 * LDA * 2);          // 36864
    const int shC256   = BM * (256 + 4) * 4;                        // 133120
    const int shC128   = BM * (128 + 4) * 4;                        // 67584
    const int smemE1   = (NSTAGE * stage256 > shC256) ? NSTAGE * stage256 : shC256;  // 165888
    const int smemE0   = NSTAGE * stage256;                         // 165888
    const int smemE2   = (NSTAGE * stage128 > shC128) ? NSTAGE * stage128 : shC128;  // 110592
    cudaFuncSetAttribute((const void*)gemm_h<256, 1, false>, cudaFuncAttributeMaxDynamicSharedMemorySize, smemE1);
    cudaFuncSetAttribute((const void*)gemm_h<256, 0, true>,  cudaFuncAttributeMaxDynamicSharedMemorySize, smemE0);
    cudaFuncSetAttribute((const void*)gemm_h<256, 0, false>, cudaFuncAttributeMaxDynamicSharedMemorySize, smemE0);
    cudaFuncSetAttribute((const void*)gemm_h<128, 2, false>, cudaFuncAttributeMaxDynamicSharedMemorySize, smemE2);

    const float inv = 1.0f / sqrtf((float)HDd);
    dim3 blk(NTHREADS);

    // 0) prep: fp32 -> half (RNE); W transposed
    f2h_copy<<<512, 256>>>((const float4*)hs, (uint2*)hsr, (Bb * Ss * Dd) / 4);
    f2h_copy<<<128, 256>>>((const float4*)de, (uint2*)der, (Ll * HDd) / 4);
    {
        dim3 b(32, 8);
        transpose_h<<<dim3(48, 48), b>>>(wq, wt);
        transpose_h<<<dim3(48, 48), b>>>(wk, wt + WN3);
        transpose_h<<<dim3(48, 48), b>>>(wv, wt + 2 * WN3);
    }

    // 1) fused QKV: hs(7360x1536) @ W^T -> q,k half (b,h,s,d) + vt half (b,h,d,s)
    dim3 gA(Dd / 256, (Bb * Ss + BM - 1) / BM, 3);                  // (6, 58, 3)
    gemm_h<256, 1, false><<<gA, blk, smemE1>>>(hsr, wt, q, Bb * Ss, Hh * HDd, Dd,
                                               0, (long long)WN3, 0, 0, inv, k, vt);

    // 2) R = Q @ DE^T : (29440 x 1839) band-restricted -> fp32, stride RST
    dim3 gR((Ll + 255) / 256, MQ / BM, 1);                          // (8, 230)
    gemm_h<256, 0, true><<<gR, blk, smemE0>>>(q, der, r, MQ, Ll, HDd,
                                              0, 0, 0, RST, 1.0f, nullptr, nullptr);

    // 3) scores = Q @ K^T per bh: 32 x (920x920) -> fp32, padded slabs
    dim3 gS(4, 8, BH);                                              // 1024x1024 padded
    gemm_h<256, 0, false><<<gS, blk, smemE0>>>(q, k, s, Ss, Ss, HDd,
                                               (long long)Ss * HDd, (long long)Ss * HDd,
                                               (long long)SZSTR, SROW, 1.0f, nullptr, nullptr);

    // 4) bias + softmax -> half probs (packed 920)
    bias_softmax<<<MQ, 256>>>(s, r, p);

    // 5) ctx = P @ Vt^T per bh -> fp32 (B,S,H*HD)
    dim3 gO(HDd / 128, (Ss + BM - 1) / BM, BH);                     // (3, 8, 32)
    gemm_h<128, 2, false><<<gO, blk, smemE2>>>(p, vt, out, Ss, HDd, Ss,
                                               (long long)Ss * Ss, (long long)HDd * Ss,
                                               0, 0, 1.0f, nullptr, nullptr);
}

// round 8
// speedup vs baseline: 6.7456x; 1.0305x over previous
#include <cuda_runtime.h>
#include <cuda_fp16.h>
#include <mma.h>
#include <math.h>
#include <cstdint>

using namespace nvcuda;

// ---------------- problem constants ----------------
#define Bb   8
#define Ss   920
#define Dd   1536
#define Hh   4
#define HDd  384
#define Ll   1839
#define BH   32
#define MQ   29440
#define HALFL 919
#define RST  2048                 // padded R row stride (halfs)
#define SROW 1024                 // padded scores row stride (fp32)
#define SZSTR (1024*1024)         // padded scores per-bh slab
#define WN3  (Dd*Hh*HDd)

// ---------------- GEMM tiling ----------------
#define BM 128
#define BNV 128
#define TK 32                     // k-depth per stage (halfs)
#define NSTAGE 3
#define NTHREADS 256
#define LDA 40                    // TK + 8 skew (halfs)

// ---------------- scratch ----------------
__device__ __half g_q[BH * Ss * HDd];
__device__ __half g_k[BH * Ss * HDd];
__device__ __half g_vt[BH * HDd * Ss];            // V^T: [bh][d][s]
__device__ __half g_r[(long long)MQ * RST];       // rel bias, HALF, padded
__device__ float  g_s[(long long)BH * SZSTR];     // scores fp32, padded slabs
__device__ __half g_p[(long long)BH * Ss * Ss];   // probs half, packed
__device__ __half g_hs[Bb * Ss * Dd];
__device__ __half g_wt[3 * WN3];                  // W^T half
__device__ __half g_de[Ll * HDd];

// ---------------- helpers ----------------
__device__ __forceinline__ uint32_t smem_u32(const void* p) {
    uint32_t a;
    asm("{ .reg .u64 t; cvta.to.shared.u64 t, %1; cvt.u32.u64 %0, t; }" : "=r"(a) : "l"(p));
    return a;
}
__device__ __forceinline__ void cp16s(uint32_t dst, const void* src, bool p) {
    int sz = p ? 16 : 0;
    asm volatile("cp.async.cg.shared.global [%0], [%1], 16, %2;\n" :: "r"(dst), "l"(src), "r"(sz));
}
__device__ __forceinline__ void cp_commit() { asm volatile("cp.async.commit_group;\n"); }
__device__ __forceinline__ void cp_wait0()  { asm volatile("cp.async.wait_group 0;\n"); }
__device__ __forceinline__ void cp_wait1()  { asm volatile("cp.async.wait_group 1;\n"); }

// ---------------- prep kernels ----------------
__global__ __launch_bounds__(256)
void f2h_copy(const float4* __restrict__ src, uint2* __restrict__ dst, int n4)
{
    int i = blockIdx.x * 256 + threadIdx.x;
    int st = gridDim.x * 256;
    for (; i < n4; i += st) {
        float4 v = src[i];
        __half2 h01 = __floats2half2_rn(v.x, v.y);
        __half2 h23 = __floats2half2_rn(v.z, v.w);
        uint2 o;
        o.x = *reinterpret_cast<uint32_t*>(&h01);
        o.y = *reinterpret_cast<uint32_t*>(&h23);
        dst[i] = o;
    }
}

__global__ __launch_bounds__(256)
void transpose_h(const float* __restrict__ src, __half* __restrict__ dst)
{
    __shared__ float t[32][33];
    int tx = threadIdx.x, ty = threadIdx.y;
    int x = blockIdx.x * 32 + tx;
    int y0 = blockIdx.y * 32;
    #pragma unroll
    for (int i = 0; i < 32; i += 8)
        t[ty + i][tx] = src[(long long)(y0 + ty + i) * 1536 + x];
    __syncthreads();
    int x2 = blockIdx.y * 32 + tx;
    int y2 = blockIdx.x * 32;
    #pragma unroll
    for (int i = 0; i < 32; i += 8)
        dst[(long long)(y2 + ty + i) * 1536 + x2] = __float2half_rn(t[tx][ty + i]);
}

// =======================================================================
// fp16 WMMA NT GEMM: C = A(MxK,row,half) * B(NxK,row,half)^T, fp32 accum.
// CTA 128x128, 8 warps (2x4), warp tile 64x32. 3-stage cp.async, TK=32.
// 2 CTAs/SM (launch_bounds + smem <= 67.6KB).
// EPI 0: fp32 direct store_matrix_sync, padded strides, no guard
// EPI 1: fused QKV (z: 0->Cv(q),1->C1(k),2->C2(vt)); scale only z==0
// EPI 2: ctx: z=(b,h): fp32 out[(b*S+gm)*1536 + h*384 + gn], guarded
// EPI 3: half output, padded row stride ldC, no guard (R)
// BAND: early-exit for R band
// =======================================================================
template<int EPI, bool BAND>
__global__ __launch_bounds__(NTHREADS, 2)
void gemm_h(const __half* __restrict__ A, const __half* __restrict__ B,
            void* __restrict__ Cv,
            int M, int N, int K,
            long long strA, long long strB, long long strC, int ldC,
            float scale, __half* __restrict__ C1, __half* __restrict__ C2)
{
    constexpr int WNv = 32;
    constexpr int NF  = 2;
    constexpr int A_BYTES = BM * LDA * 2;
    constexpr int B_BYTES = BNV * LDA * 2;
    constexpr int STAGE_BYTES = A_BYTES + B_BYTES;   // 20480
    constexpr int LDC = BNV + 4;

    const int m0 = blockIdx.y * BM;
    const int n0 = blockIdx.x * BNV;

    if (BAND) {
        int mq0 = m0 % Ss;
        int qlo, qhi;
        if (mq0 + (BM - 1) < Ss) { qlo = mq0; qhi = mq0 + BM - 1; }
        else                     { qlo = 0;   qhi = Ss - 1; }
        int lmin = HALFL - qhi, lmax = (Ll - 1) - qlo;
        if (n0 > lmax || n0 + BNV - 1 < lmin) return;
    }

    extern __shared__ char smem[];
    const uint32_t sb = smem_u32(smem);

    const int tid  = threadIdx.x;
    const int warp = tid >> 5;
    const int wm   = warp >> 2;
    const int wn   = warp & 3;
    const int z    = blockIdx.z;

    A += (long long)z * strA;
    B += (long long)z * strB;
    if (EPI == 1 && z != 0) scale = 1.0f;

    const int nIter = (K + TK - 1) / TK;

    wmma::fragment<wmma::accumulator, 16, 16, 16, float> acc[4][NF];
    #pragma unroll
    for (int i = 0; i < 4; i++)
        #pragma unroll
        for (int j = 0; j < NF; j++)
            wmma::fill_fragment(acc[i][j], 0.0f);

    auto issue_stage = [&](int s) {
        const uint32_t base = sb + (uint32_t)(s % NSTAGE) * STAGE_BYTES;
        const int k0 = s * TK;
        // A tile: 128 x 32 halfs = 512 16B-chunks
        #pragma unroll
        for (int t = 0; t < 2; t++) {
            int idx = tid + t * NTHREADS;
            int r = idx >> 2, c = idx & 3;
            int gm = m0 + r, gk = k0 + c * 8;
            bool p = (gm < M) && (gk < K);
            const __half* src = A + (long long)(p ? gm : 0) * K + (p ? gk : 0);
            cp16s(base + (uint32_t)(r * (LDA * 2) + c * 16), src, p);
        }
        // B tile: 128 x 32 halfs
        #pragma unroll
        for (int t = 0; t < 2; t++) {
            int idx = tid + t * NTHREADS;
            int r = idx >> 2, c = idx & 3;
            int gn = n0 + r, gk = k0 + c * 8;
            bool p = (gn < N) && (gk < K);
            const __half* src = B + (long long)(p ? gn : 0) * K + (p ? gk : 0);
            cp16s(base + (uint32_t)A_BYTES + (uint32_t)(r * (LDA * 2) + c * 16), src, p);
        }
        cp_commit();
    };

    issue_stage(0);
    issue_stage(1);

    for (int it = 0; it < nIter; ++it) {
        const __half* cA = (const __half*)(smem + (it % NSTAGE) * STAGE_BYTES);
        const __half* cB = (const __half*)(smem + (it % NSTAGE) * STAGE_BYTES + A_BYTES);

        if (it + 1 < nIter) cp_wait1(); else cp_wait0();
        __syncthreads();
        if (it + 2 < nIter) issue_stage(it + 2);

        #pragma unroll
        for (int kk = 0; kk < TK; kk += 16) {
            wmma::fragment<wmma::matrix_a, 16, 16, 16, __half, wmma::row_major> af[4];
            #pragma unroll
            for (int i = 0; i < 4; i++)
                wmma::load_matrix_sync(af[i], cA + (wm * 64 + i * 16) * LDA + kk, LDA);
            wmma::fragment<wmma::matrix_b, 16, 16, 16, __half, wmma::col_major> bf[NF];
            #pragma unroll
            for (int j = 0; j < NF; j++)
                wmma::load_matrix_sync(bf[j], cB + (wn * WNv + j * 16) * LDA + kk, LDA);
            #pragma unroll
            for (int i = 0; i < 4; i++)
                #pragma unroll
                for (int j = 0; j < NF; j++)
                    wmma::mma_sync(acc[i][j], af[i], bf[j], acc[i][j]);
        }
    }

    if (EPI == 0) {
        float* Cg = (float*)Cv + (long long)z * strC;
        #pragma unroll
        for (int i = 0; i < 4; i++) {
            int gm = m0 + wm * 64 + i * 16;
            #pragma unroll
            for (int j = 0; j < NF; j++) {
                int gn = n0 + wn * WNv + j * 16;
                wmma::store_matrix_sync(Cg + (long long)gm * ldC + gn,
                                        acc[i][j], ldC, wmma::mem_row_major);
            }
        }
        return;
    }

    __syncthreads();
    float* shC = (float*)smem;   // [BM][LDC]
    #pragma unroll
    for (int i = 0; i < 4; i++)
        #pragma unroll
        for (int j = 0; j < NF; j++)
            wmma::store_matrix_sync(&shC[(wm * 64 + i * 16) * LDC + (wn * WNv + j * 16)],
                                    acc[i][j], LDC, wmma::mem_row_major);
    __syncthreads();

    if (EPI == 3) {
        // half, unguarded (caller guarantees padded stride and exact M)
        __half* Cg = (__half*)Cv;
        #pragma unroll 4
        for (int idx = tid; idx < BM * BNV; idx += NTHREADS) {
            int i = idx >> 7, j = idx & 127;
            Cg[(long long)(m0 + i) * ldC + (n0 + j)] = __float2half_rn(shC[i * LDC + j]);
        }
    } else if (EPI == 1 && z == 2) {
        #pragma unroll 4
        for (int idx = tid; idx < BM * BNV; idx += NTHREADS) {
            int i = idx & (BM - 1), j = idx >> 7;
            int gm = m0 + i, gn = n0 + j;
            if (gm >= M || gn >= N) continue;
            float v = shC[i * LDC + j];
            int b2 = gm / Ss, sP = gm - b2 * Ss;
            int h = gn / HDd, d = gn - h * HDd;
            C2[(((long long)(b2 * Hh + h)) * HDd + d) * Ss + sP] = __float2half_rn(v);
        }
    } else {
        #pragma unroll 4
        for (int idx = tid; idx < BM * BNV; idx += NTHREADS) {
            int i = idx >> 7, j = idx & 127;
            int gm = m0 + i, gn = n0 + j;
            if (gm >= M || gn >= N) continue;
            float v = shC[i * LDC + j] * scale;
            if (EPI == 1) {
                int b2 = gm / Ss, sP = gm - b2 * Ss;
                int h = gn / HDd, d = gn - h * HDd;
                __half hv = __float2half_rn(v);
                long long o = (((long long)(b2 * Hh + h)) * Ss + sP) * HDd + d;
                if (z == 0) ((__half*)Cv)[o] = hv; else C1[o] = hv;
            } else { // EPI == 2
                int b2 = z >> 2, h = z & 3;
                ((float*)Cv)[((long long)b2 * Ss + gm) * (Hh * HDd) + h * HDd + gn] = v;
            }
        }
    }
}

// =======================================================================
// bias + softmax: scores[bh,q,k] += R_half[m, k-q+919]; softmax; half probs
// =======================================================================
__global__ __launch_bounds__(256)
void bias_softmax(const float* __restrict__ sc, const __half* __restrict__ R,
                  __half* __restrict__ P)
{
    const int r = blockIdx.x;
    const int bh = r / Ss, q = r - bh * Ss;
    const float* row = sc + (long long)bh * SZSTR + (long long)q * SROW;
    const __half* rrow = R + (long long)r * RST + (HALFL - q);
    __half* prow = P + (long long)r * Ss;

    const int tid = threadIdx.x, lane = tid & 31, wid = tid >> 5;
    __shared__ float wred[8];

    float vals[4];
    float mx = -1e30f;
    #pragma unroll
    for (int i = 0; i < 4; i++) {
        int k = tid + i * 256;
        float v = -1e30f;
        if (k < Ss) v = row[k] + __half2float(rrow[k]);
        vals[i] = v;
        mx = fmaxf(mx, v);
    }
    #pragma unroll
    for (int o = 16; o > 0; o >>= 1) mx = fmaxf(mx, __shfl_xor_sync(0xffffffffu, mx, o));
    if (lane == 0) wred[wid] = mx;
    __syncthreads();
    mx = wred[0];
    #pragma unroll
    for (int w = 1; w < 8; w++) mx = fmaxf(mx, wred[w]);
    __syncthreads();

    float sum = 0.0f;
    #pragma unroll
    for (int i = 0; i < 4; i++) {
        int k = tid + i * 256;
        float e = 0.0f;
        if (k < Ss) e = __expf(vals[i] - mx);
        vals[i] = e;
        sum += e;
    }
    #pragma unroll
    for (int o = 16; o > 0; o >>= 1) sum += __shfl_xor_sync(0xffffffffu, sum, o);
    if (lane == 0) wred[wid] = sum;
    __syncthreads();
    sum = 0.0f;
    #pragma unroll
    for (int w = 0; w < 8; w++) sum += wred[w];

    const float inv = 1.0f / sum;
    #pragma unroll
    for (int i = 0; i < 4; i++) {
        int k = tid + i * 256;
        if (k < Ss) prow[k] = __float2half_rn(vals[i] * inv);
    }
}

// =======================================================================
extern "C" void kernel_launch(void* const* d_in, const int* in_sizes, int n_in,
                              void* d_out, int out_size)
{
    (void)in_sizes; (void)n_in; (void)out_size;
    const float* hs = (const float*)d_in[0];
    const float* wq = (const float*)d_in[1];
    const float* wk = (const float*)d_in[2];
    const float* wv = (const float*)d_in[3];
    const float* de = (const float*)d_in[4];
    float* out = (float*)d_out;

    __half *q, *k, *vt, *p, *hsr, *wt, *der, *r;
    float *s;
    cudaGetSymbolAddress((void**)&q,   g_q);
    cudaGetSymbolAddress((void**)&k,   g_k);
    cudaGetSymbolAddress((void**)&vt,  g_vt);
    cudaGetSymbolAddress((void**)&r,   g_r);
    cudaGetSymbolAddress((void**)&s,   g_s);
    cudaGetSymbolAddress((void**)&p,   g_p);
    cudaGetSymbolAddress((void**)&hsr, g_hs);
    cudaGetSymbolAddress((void**)&wt,  g_wt);
    cudaGetSymbolAddress((void**)&der, g_de);

    const int stage3 = NSTAGE * ((BM + BNV) * LDA * 2);             // 61440
    const int shC    = BM * (BNV + 4) * 4;                          // 67584
    const int smemST = (stage3 > shC) ? stage3 : shC;               // 67584
    cudaFuncSetAttribute((const void*)gemm_h<1, false>, cudaFuncAttributeMaxDynamicSharedMemorySize, smemST);
    cudaFuncSetAttribute((const void*)gemm_h<3, true>,  cudaFuncAttributeMaxDynamicSharedMemorySize, smemST);
    cudaFuncSetAttribute((const void*)gemm_h<0, false>, cudaFuncAttributeMaxDynamicSharedMemorySize, stage3);
    cudaFuncSetAttribute((const void*)gemm_h<2, false>, cudaFuncAttributeMaxDynamicSharedMemorySize, smemST);

    const float inv = 1.0f / sqrtf((float)HDd);
    dim3 blk(NTHREADS);

    // 0) prep
    f2h_copy<<<512, 256>>>((const float4*)hs, (uint2*)hsr, (Bb * Ss * Dd) / 4);
    f2h_copy<<<128, 256>>>((const float4*)de, (uint2*)der, (Ll * HDd) / 4);
    {
        dim3 b(32, 8);
        transpose_h<<<dim3(48, 48), b>>>(wq, wt);
        transpose_h<<<dim3(48, 48), b>>>(wk, wt + WN3);
        transpose_h<<<dim3(48, 48), b>>>(wv, wt + 2 * WN3);
    }

    // 1) fused QKV
    dim3 gA(Dd / BNV, (Bb * Ss + BM - 1) / BM, 3);                  // (12, 58, 3)
    gemm_h<1, false><<<gA, blk, smemST>>>(hsr, wt, q, Bb * Ss, Hh * HDd, Dd,
                                          0, (long long)WN3, 0, 0, inv, k, vt);

    // 2) R = Q @ DE^T (banded) -> half, stride RST, unguarded padded stores
    dim3 gR((Ll + BNV - 1) / BNV, MQ / BM, 1);                      // (15, 230)
    gemm_h<3, true><<<gR, blk, smemST>>>(q, der, r, MQ, Ll, HDd,
                                         0, 0, 0, RST, 1.0f, nullptr, nullptr);

    // 3) scores = Q @ K^T per bh -> fp32 padded slabs, direct stores
    dim3 gS(8, 8, BH);                                              // 1024x1024 padded
    gemm_h<0, false><<<gS, blk, stage3>>>(q, k, s, Ss, Ss, HDd,
                                          (long long)Ss * HDd, (long long)Ss * HDd,
                                          (long long)SZSTR, SROW, 1.0f, nullptr, nullptr);

    // 4) bias + softmax -> half probs
    bias_softmax<<<MQ, 256>>>(s, r, p);

    // 5) ctx = P @ Vt^T per bh -> fp32 (B,S,H*HD)
    dim3 gO(HDd / BNV, (Ss + BM - 1) / BM, BH);                     // (3, 8, 32)
    gemm_h<2, false><<<gO, blk, smemST>>>(p, vt, out, Ss, HDd, Ss,
                                          (long long)Ss * Ss, (long long)HDd * Ss,
                                          0, 0, 1.0f, nullptr, nullptr);
}

// round 9
// speedup vs baseline: 7.4066x; 1.0980x over previous
#include <cuda_runtime.h>
#include <cuda_fp16.h>
#include <mma.h>
#include <math.h>
#include <cstdint>

using namespace nvcuda;

// ---------------- problem constants ----------------
#define Bb   8
#define Ss   920
#define Dd   1536
#define Hh   4
#define HDd  384
#define Ll   1839
#define BH   32
#define MQ   29440
#define HALFL 919
#define RST  2048                 // padded R row stride (halfs)
#define SROW 1024                 // padded scores row stride (fp32)
#define SZSTR (1024*1024)         // padded scores per-bh slab
#define WN3  (Dd*Hh*HDd)

// ---------------- GEMM tiling ----------------
#define BM 128
#define BNV 128
#define TK 64                     // k-depth per stage (halfs)
#define NSTAGE 3
#define NTHREADS 256
#define LDA 72                    // TK + 8 skew (halfs)

// ---------------- scratch ----------------
__device__ __half g_q[BH * Ss * HDd];
__device__ __half g_k[BH * Ss * HDd];
__device__ __half g_vt[BH * HDd * Ss];            // V^T: [bh][d][s]
__device__ __half g_r[(long long)MQ * RST];       // rel bias, HALF, padded
__device__ float  g_s[(long long)BH * SZSTR];     // scores fp32, padded slabs
__device__ __half g_p[(long long)BH * Ss * Ss];   // probs half, packed
__device__ __half g_hs[Bb * Ss * Dd];
__device__ __half g_wt[3 * WN3];                  // W^T half
__device__ __half g_de[Ll * HDd];

// ---------------- helpers ----------------
__device__ __forceinline__ uint32_t smem_u32(const void* p) {
    uint32_t a;
    asm("{ .reg .u64 t; cvta.to.shared.u64 t, %1; cvt.u32.u64 %0, t; }" : "=r"(a) : "l"(p));
    return a;
}
__device__ __forceinline__ void cp16s(uint32_t dst, const void* src, bool p) {
    int sz = p ? 16 : 0;
    asm volatile("cp.async.cg.shared.global [%0], [%1], 16, %2;\n" :: "r"(dst), "l"(src), "r"(sz));
}
__device__ __forceinline__ void cp_commit() { asm volatile("cp.async.commit_group;\n"); }
__device__ __forceinline__ void cp_wait0()  { asm volatile("cp.async.wait_group 0;\n"); }
__device__ __forceinline__ void cp_wait1()  { asm volatile("cp.async.wait_group 1;\n"); }

// ---------------- prep kernels ----------------
__global__ __launch_bounds__(256)
void f2h_copy(const float4* __restrict__ src, uint2* __restrict__ dst, int n4)
{
    int i = blockIdx.x * 256 + threadIdx.x;
    int st = gridDim.x * 256;
    for (; i < n4; i += st) {
        float4 v = src[i];
        __half2 h01 = __floats2half2_rn(v.x, v.y);
        __half2 h23 = __floats2half2_rn(v.z, v.w);
        uint2 o;
        o.x = *reinterpret_cast<uint32_t*>(&h01);
        o.y = *reinterpret_cast<uint32_t*>(&h23);
        dst[i] = o;
    }
}

// fused: all three W (1536x1536) -> W^T half slabs; z selects matrix
__global__ __launch_bounds__(256)
void transpose_h3(const float* __restrict__ w0, const float* __restrict__ w1,
                  const float* __restrict__ w2, __half* __restrict__ dst)
{
    __shared__ float t[32][33];
    const int z = blockIdx.z;
    const float* src = (z == 0) ? w0 : (z == 1) ? w1 : w2;
    __half* d = dst + (long long)z * WN3;
    int tx = threadIdx.x, ty = threadIdx.y;
    int x = blockIdx.x * 32 + tx;
    int y0 = blockIdx.y * 32;
    #pragma unroll
    for (int i = 0; i < 32; i += 8)
        t[ty + i][tx] = src[(long long)(y0 + ty + i) * 1536 + x];
    __syncthreads();
    int x2 = blockIdx.y * 32 + tx;
    int y2 = blockIdx.x * 32;
    #pragma unroll
    for (int i = 0; i < 32; i += 8)
        d[(long long)(y2 + ty + i) * 1536 + x2] = __float2half_rn(t[tx][ty + i]);
}

// =======================================================================
// fp16 WMMA NT GEMM: C = A(MxK,row,half) * B(NxK,row,half)^T, fp32 accum.
// CTA 128x128, 8 warps (2x4), warp tile 64x32. 3-stage cp.async, TK=64.
// 2 CTAs/SM (smem 110.6KB/CTA -> 221KB/SM on B300's 228KB).
// EPI 0: fp32 direct store_matrix_sync, padded strides, no guard
// EPI 1: fused QKV (z: 0->Cv(q),1->C1(k),2->C2(vt)); scale only z==0
// EPI 2: ctx: z=(b,h): fp32 out[(b*S+gm)*1536 + h*384 + gn], guarded
// EPI 3: half output, padded row stride ldC, no guard (R)
// BAND: early-exit for R band
// =======================================================================
template<int EPI, bool BAND>
__global__ __launch_bounds__(NTHREADS, 2)
void gemm_h(const __half* __restrict__ A, const __half* __restrict__ B,
            void* __restrict__ Cv,
            int M, int N, int K,
            long long strA, long long strB, long long strC, int ldC,
            float scale, __half* __restrict__ C1, __half* __restrict__ C2)
{
    constexpr int WNv = 32;
    constexpr int NF  = 2;
    constexpr int A_BYTES = BM * LDA * 2;
    constexpr int B_BYTES = BNV * LDA * 2;
    constexpr int STAGE_BYTES = A_BYTES + B_BYTES;   // 36864
    constexpr int LDC = BNV + 4;

    const int m0 = blockIdx.y * BM;
    const int n0 = blockIdx.x * BNV;

    if (BAND) {
        int mq0 = m0 % Ss;
        int qlo, qhi;
        if (mq0 + (BM - 1) < Ss) { qlo = mq0; qhi = mq0 + BM - 1; }
        else                     { qlo = 0;   qhi = Ss - 1; }
        int lmin = HALFL - qhi, lmax = (Ll - 1) - qlo;
        if (n0 > lmax || n0 + BNV - 1 < lmin) return;
    }

    extern __shared__ char smem[];
    const uint32_t sb = smem_u32(smem);

    const int tid  = threadIdx.x;
    const int warp = tid >> 5;
    const int wm   = warp >> 2;
    const int wn   = warp & 3;
    const int z    = blockIdx.z;

    A += (long long)z * strA;
    B += (long long)z * strB;
    if (EPI == 1 && z != 0) scale = 1.0f;

    const int nIter = (K + TK - 1) / TK;

    wmma::fragment<wmma::accumulator, 16, 16, 16, float> acc[4][NF];
    #pragma unroll
    for (int i = 0; i < 4; i++)
        #pragma unroll
        for (int j = 0; j < NF; j++)
            wmma::fill_fragment(acc[i][j], 0.0f);

    auto issue_stage = [&](int s) {
        const uint32_t base = sb + (uint32_t)(s % NSTAGE) * STAGE_BYTES;
        const int k0 = s * TK;
        // A tile: 128 x 64 halfs = 1024 16B-chunks
        #pragma unroll
        for (int t = 0; t < 4; t++) {
            int idx = tid + t * NTHREADS;
            int r = idx >> 3, c = idx & 7;
            int gm = m0 + r, gk = k0 + c * 8;
            bool p = (gm < M) && (gk < K);
            const __half* src = A + (long long)(p ? gm : 0) * K + (p ? gk : 0);
            cp16s(base + (uint32_t)(r * (LDA * 2) + c * 16), src, p);
        }
        // B tile: 128 x 64 halfs
        #pragma unroll
        for (int t = 0; t < 4; t++) {
            int idx = tid + t * NTHREADS;
            int r = idx >> 3, c = idx & 7;
            int gn = n0 + r, gk = k0 + c * 8;
            bool p = (gn < N) && (gk < K);
            const __half* src = B + (long long)(p ? gn : 0) * K + (p ? gk : 0);
            cp16s(base + (uint32_t)A_BYTES + (uint32_t)(r * (LDA * 2) + c * 16), src, p);
        }
        cp_commit();
    };

    issue_stage(0);
    issue_stage(1);

    for (int it = 0; it < nIter; ++it) {
        const __half* cA = (const __half*)(smem + (it % NSTAGE) * STAGE_BYTES);
        const __half* cB = (const __half*)(smem + (it % NSTAGE) * STAGE_BYTES + A_BYTES);

        if (it + 1 < nIter) cp_wait1(); else cp_wait0();
        __syncthreads();
        if (it + 2 < nIter) issue_stage(it + 2);

        #pragma unroll
        for (int kk = 0; kk < TK; kk += 16) {
            wmma::fragment<wmma::matrix_a, 16, 16, 16, __half, wmma::row_major> af[4];
            #pragma unroll
            for (int i = 0; i < 4; i++)
                wmma::load_matrix_sync(af[i], cA + (wm * 64 + i * 16) * LDA + kk, LDA);
            wmma::fragment<wmma::matrix_b, 16, 16, 16, __half, wmma::col_major> bf[NF];
            #pragma unroll
            for (int j = 0; j < NF; j++)
                wmma::load_matrix_sync(bf[j], cB + (wn * WNv + j * 16) * LDA + kk, LDA);
            #pragma unroll
            for (int i = 0; i < 4; i++)
                #pragma unroll
                for (int j = 0; j < NF; j++)
                    wmma::mma_sync(acc[i][j], af[i], bf[j], acc[i][j]);
        }
    }

    if (EPI == 0) {
        float* Cg = (float*)Cv + (long long)z * strC;
        #pragma unroll
        for (int i = 0; i < 4; i++) {
            int gm = m0 + wm * 64 + i * 16;
            #pragma unroll
            for (int j = 0; j < NF; j++) {
                int gn = n0 + wn * WNv + j * 16;
                wmma::store_matrix_sync(Cg + (long long)gm * ldC + gn,
                                        acc[i][j], ldC, wmma::mem_row_major);
            }
        }
        return;
    }

    __syncthreads();
    float* shC = (float*)smem;   // [BM][LDC]
    #pragma unroll
    for (int i = 0; i < 4; i++)
        #pragma unroll
        for (int j = 0; j < NF; j++)
            wmma::store_matrix_sync(&shC[(wm * 64 + i * 16) * LDC + (wn * WNv + j * 16)],
                                    acc[i][j], LDC, wmma::mem_row_major);
    __syncthreads();

    if (EPI == 3) {
        __half* Cg = (__half*)Cv;
        #pragma unroll 4
        for (int idx = tid; idx < BM * BNV; idx += NTHREADS) {
            int i = idx >> 7, j = idx & 127;
            Cg[(long long)(m0 + i) * ldC + (n0 + j)] = __float2half_rn(shC[i * LDC + j]);
        }
    } else if (EPI == 1 && z == 2) {
        #pragma unroll 4
        for (int idx = tid; idx < BM * BNV; idx += NTHREADS) {
            int i = idx & (BM - 1), j = idx >> 7;
            int gm = m0 + i, gn = n0 + j;
            if (gm >= M || gn >= N) continue;
            float v = shC[i * LDC + j];
            int b2 = gm / Ss, sP = gm - b2 * Ss;
            int h = gn / HDd, d = gn - h * HDd;
            C2[(((long long)(b2 * Hh + h)) * HDd + d) * Ss + sP] = __float2half_rn(v);
        }
    } else {
        #pragma unroll 4
        for (int idx = tid; idx < BM * BNV; idx += NTHREADS) {
            int i = idx >> 7, j = idx & 127;
            int gm = m0 + i, gn = n0 + j;
            if (gm >= M || gn >= N) continue;
            float v = shC[i * LDC + j] * scale;
            if (EPI == 1) {
                int b2 = gm / Ss, sP = gm - b2 * Ss;
                int h = gn / HDd, d = gn - h * HDd;
                __half hv = __float2half_rn(v);
                long long o = (((long long)(b2 * Hh + h)) * Ss + sP) * HDd + d;
                if (z == 0) ((__half*)Cv)[o] = hv; else C1[o] = hv;
            } else { // EPI == 2
                int b2 = z >> 2, h = z & 3;
                ((float*)Cv)[((long long)b2 * Ss + gm) * (Hh * HDd) + h * HDd + gn] = v;
            }
        }
    }
}

// =======================================================================
// bias + softmax: scores[bh,q,k] += R_half[m, k-q+919]; softmax; half probs
// =======================================================================
__global__ __launch_bounds__(256)
void bias_softmax(const float* __restrict__ sc, const __half* __restrict__ R,
                  __half* __restrict__ P)
{
    const int r = blockIdx.x;
    const int bh = r / Ss, q = r - bh * Ss;
    const float* row = sc + (long long)bh * SZSTR + (long long)q * SROW;
    const __half* rrow = R + (long long)r * RST + (HALFL - q);
    __half* prow = P + (long long)r * Ss;

    const int tid = threadIdx.x, lane = tid & 31, wid = tid >> 5;
    __shared__ float wred[8];

    float vals[4];
    float mx = -1e30f;
    #pragma unroll
    for (int i = 0; i < 4; i++) {
        int k = tid + i * 256;
        float v = -1e30f;
        if (k < Ss) v = row[k] + __half2float(rrow[k]);
        vals[i] = v;
        mx = fmaxf(mx, v);
    }
    #pragma unroll
    for (int o = 16; o > 0; o >>= 1) mx = fmaxf(mx, __shfl_xor_sync(0xffffffffu, mx, o));
    if (lane == 0) wred[wid] = mx;
    __syncthreads();
    mx = wred[0];
    #pragma unroll
    for (int w = 1; w < 8; w++) mx = fmaxf(mx, wred[w]);
    __syncthreads();

    float sum = 0.0f;
    #pragma unroll
    for (int i = 0; i < 4; i++) {
        int k = tid + i * 256;
        float e = 0.0f;
        if (k < Ss) e = __expf(vals[i] - mx);
        vals[i] = e;
        sum += e;
    }
    #pragma unroll
    for (int o = 16; o > 0; o >>= 1) sum += __shfl_xor_sync(0xffffffffu, sum, o);
    if (lane == 0) wred[wid] = sum;
    __syncthreads();
    sum = 0.0f;
    #pragma unroll
    for (int w = 0; w < 8; w++) sum += wred[w];

    const float inv = 1.0f / sum;
    #pragma unroll
    for (int i = 0; i < 4; i++) {
        int k = tid + i * 256;
        if (k < Ss) prow[k] = __float2half_rn(vals[i] * inv);
    }
}

// =======================================================================
extern "C" void kernel_launch(void* const* d_in, const int* in_sizes, int n_in,
                              void* d_out, int out_size)
{
    (void)in_sizes; (void)n_in; (void)out_size;
    const float* hs = (const float*)d_in[0];
    const float* wq = (const float*)d_in[1];
    const float* wk = (const float*)d_in[2];
    const float* wv = (const float*)d_in[3];
    const float* de = (const float*)d_in[4];
    float* out = (float*)d_out;

    __half *q, *k, *vt, *p, *hsr, *wt, *der, *r;
    float *s;
    cudaGetSymbolAddress((void**)&q,   g_q);
    cudaGetSymbolAddress((void**)&k,   g_k);
    cudaGetSymbolAddress((void**)&vt,  g_vt);
    cudaGetSymbolAddress((void**)&r,   g_r);
    cudaGetSymbolAddress((void**)&s,   g_s);
    cudaGetSymbolAddress((void**)&p,   g_p);
    cudaGetSymbolAddress((void**)&hsr, g_hs);
    cudaGetSymbolAddress((void**)&wt,  g_wt);
    cudaGetSymbolAddress((void**)&der, g_de);

    const int stage3 = NSTAGE * ((BM + BNV) * LDA * 2);             // 110592
    const int shC    = BM * (BNV + 4) * 4;                          // 67584
    const int smemST = (stage3 > shC) ? stage3 : shC;               // 110592
    cudaFuncSetAttribute((const void*)gemm_h<1, false>, cudaFuncAttributeMaxDynamicSharedMemorySize, smemST);
    cudaFuncSetAttribute((const void*)gemm_h<3, true>,  cudaFuncAttributeMaxDynamicSharedMemorySize, smemST);
    cudaFuncSetAttribute((const void*)gemm_h<0, false>, cudaFuncAttributeMaxDynamicSharedMemorySize, smemST);
    cudaFuncSetAttribute((const void*)gemm_h<2, false>, cudaFuncAttributeMaxDynamicSharedMemorySize, smemST);

    const float inv = 1.0f / sqrtf((float)HDd);
    dim3 blk(NTHREADS);

    // 0) prep
    f2h_copy<<<512, 256>>>((const float4*)hs, (uint2*)hsr, (Bb * Ss * Dd) / 4);
    f2h_copy<<<128, 256>>>((const float4*)de, (uint2*)der, (Ll * HDd) / 4);
    transpose_h3<<<dim3(48, 48, 3), dim3(32, 8)>>>(wq, wk, wv, wt);

    // 1) fused QKV
    dim3 gA(Dd / BNV, (Bb * Ss + BM - 1) / BM, 3);                  // (12, 58, 3)
    gemm_h<1, false><<<gA, blk, smemST>>>(hsr, wt, q, Bb * Ss, Hh * HDd, Dd,
                                          0, (long long)WN3, 0, 0, inv, k, vt);

    // 2) R = Q @ DE^T (banded) -> half, stride RST, unguarded padded stores
    dim3 gR((Ll + BNV - 1) / BNV, MQ / BM, 1);                      // (15, 230)
    gemm_h<3, true><<<gR, blk, smemST>>>(q, der, r, MQ, Ll, HDd,
                                         0, 0, 0, RST, 1.0f, nullptr, nullptr);

    // 3) scores = Q @ K^T per bh -> fp32 padded slabs, direct stores
    dim3 gS(8, 8, BH);
    gemm_h<0, false><<<gS, blk, smemST>>>(q, k, s, Ss, Ss, HDd,
                                          (long long)Ss * HDd, (long long)Ss * HDd,
                                          (long long)SZSTR, SROW, 1.0f, nullptr, nullptr);

    // 4) bias + softmax -> half probs
    bias_softmax<<<MQ, 256>>>(s, r, p);

    // 5) ctx = P @ Vt^T per bh -> fp32 (B,S,H*HD)
    dim3 gO(HDd / BNV, (Ss + BM - 1) / BM, BH);                     // (3, 8, 32)
    gemm_h<2, false><<<gO, blk, smemST>>>(p, vt, out, Ss, HDd, Ss,
                                          (long long)Ss * Ss, (long long)HDd * Ss,
                                          0, 0, 1.0f, nullptr, nullptr);
}